// round 5
// baseline (speedup 1.0000x reference)
#include <cuda_runtime.h>
#include <cstdint>

#define BB 4
#define SS 2048
#define DD 1024
#define HH 16
#define HD 64
#define NTOK (BB*SS)          // 8192

// ---------------- scratch (device globals; no allocation) ----------------
__device__ float g_Q[(size_t)BB*HH*SS*HD];     // [B,H,S,HD]
__device__ float g_K[(size_t)BB*HH*SS*HD];
__device__ float g_V[(size_t)BB*HH*SS*HD];
__device__ float g_ctx[(size_t)NTOK*DD];       // [B,S,D]
__device__ float g_ln[(size_t)NTOK*DD];        // [B,S,D]

// ---------------- tf32 mma helpers ----------------
__device__ __forceinline__ uint32_t f2tf(float x) {
    uint32_t u; asm("cvt.rna.tf32.f32 %0, %1;" : "=r"(u) : "f"(x)); return u;
}
__device__ __forceinline__ void mma8(float d[4], const uint32_t a[4], const uint32_t b[2]) {
    asm("mma.sync.aligned.m16n8k8.row.col.f32.tf32.tf32.f32 "
        "{%0,%1,%2,%3}, {%4,%5,%6,%7}, {%8,%9}, {%0,%1,%2,%3};"
        : "+f"(d[0]), "+f"(d[1]), "+f"(d[2]), "+f"(d[3])
        : "r"(a[0]), "r"(a[1]), "r"(a[2]), "r"(a[3]), "r"(b[0]), "r"(b[1]));
}

// =========================================================================
// Dense GEMM: CTA 128x256x32, 256 thr (8 warps = 2m x 4n), warp 64x64.
// Plain-layout smem tiles, stride 36 words (36 mod 32 == 4 -> frag LDS.32
// bank = 4g+qd = lane, conflict-free).
// =========================================================================
#define DST 36
#define DSM_BYTES ((128*DST + 256*DST) * 4)   // 55296

template<int IS_OUT>
__device__ __forceinline__ void dense_gemm_body(
    const float* __restrict__ Asrc, const float* __restrict__ W,
    uint32_t* Ap, uint32_t* Bp,
    float acc[4][8][4], int m0, int n0)
{
    const int t    = threadIdx.x;
    const int lane = t & 31;
    const int w    = t >> 5;
    const int wm   = w >> 2;
    const int wn   = w & 3;
    const int g    = lane >> 2;
    const int qd   = lane & 3;

    for (int k0 = 0; k0 < DD; k0 += 32) {
        __syncthreads();
        // stage A: 128x32 = 1024 float4, 4 per thread
#pragma unroll
        for (int i = 0; i < 4; i++) {
            int idx = t + i * 256;
            int row = idx >> 3, kc = idx & 7;
            float4 v = *(const float4*)&Asrc[(size_t)(m0 + row) * DD + k0 + kc * 4];
            uint4 u = {f2tf(v.x), f2tf(v.y), f2tf(v.z), f2tf(v.w)};
            *(uint4*)&Ap[row * DST + kc * 4] = u;
        }
        // stage B: 256x32 = 2048 float4, 8 per thread
#pragma unroll
        for (int i = 0; i < 8; i++) {
            int idx = t + i * 256;
            int row = idx >> 3, kc = idx & 7;
            float4 v = *(const float4*)&W[(size_t)(n0 + row) * DD + k0 + kc * 4];
            uint4 u = {f2tf(v.x), f2tf(v.y), f2tf(v.z), f2tf(v.w)};
            *(uint4*)&Bp[row * DST + kc * 4] = u;
        }
        __syncthreads();

#pragma unroll
        for (int kt = 0; kt < 4; kt++) {
            uint32_t a[4][4], b[8][2];
            const int ab = (wm * 64 + g) * DST + kt * 8 + qd;
#pragma unroll
            for (int mt = 0; mt < 4; mt++) {
                int p = ab + mt * 16 * DST;
                a[mt][0] = Ap[p];
                a[mt][1] = Ap[p + 8 * DST];
                a[mt][2] = Ap[p + 4];
                a[mt][3] = Ap[p + 8 * DST + 4];
            }
            const int bb = (wn * 64 + g) * DST + kt * 8 + qd;
#pragma unroll
            for (int nt = 0; nt < 8; nt++) {
                int p = bb + nt * 8 * DST;
                b[nt][0] = Bp[p];
                b[nt][1] = Bp[p + 4];
            }
#pragma unroll
            for (int mt = 0; mt < 4; mt++)
#pragma unroll
                for (int nt = 0; nt < 8; nt++)
                    mma8(acc[mt][nt], a[mt], b[nt]);
        }
    }
}

__global__ __launch_bounds__(256, 1) void qkv_mma(
    const float* __restrict__ X,
    const float* __restrict__ Wq, const float* __restrict__ bq,
    const float* __restrict__ Wk, const float* __restrict__ bk,
    const float* __restrict__ Wv, const float* __restrict__ bv)
{
    const float* W; const float* bias; float* out;
    if (blockIdx.z == 0)      { W = Wq; bias = bq; out = g_Q; }
    else if (blockIdx.z == 1) { W = Wk; bias = bk; out = g_K; }
    else                      { W = Wv; bias = bv; out = g_V; }

    extern __shared__ uint32_t dsm[];
    uint32_t* Ap = dsm;
    uint32_t* Bp = dsm + 128 * DST;

    const int t    = threadIdx.x;
    const int lane = t & 31;
    const int w    = t >> 5;
    const int wm   = w >> 2;
    const int wn   = w & 3;
    const int g    = lane >> 2;
    const int qd   = lane & 3;
    const int m0   = blockIdx.x * 128;
    const int n0   = blockIdx.y * 256;

    float acc[4][8][4];
#pragma unroll
    for (int mt = 0; mt < 4; mt++)
#pragma unroll
        for (int nt = 0; nt < 8; nt++)
#pragma unroll
            for (int e = 0; e < 4; e++) acc[mt][nt][e] = 0.f;

    dense_gemm_body<0>(X, W, Ap, Bp, acc, m0, n0);

    // epilogue: bias add, scatter to [B,H,S,HD]
    const int bidx  = m0 >> 11;
    const int sbase = m0 & (SS - 1);
#pragma unroll
    for (int nt = 0; nt < 8; nt++) {
        int col = n0 + wn * 64 + nt * 8 + qd * 2;
        int h = col >> 6, d = col & 63;
        float bx = bias[col], by = bias[col + 1];
        float* obase = out + ((size_t)(bidx * HH + h) * SS) * HD + d;
#pragma unroll
        for (int mt = 0; mt < 4; mt++) {
            int s = sbase + wm * 64 + mt * 16 + g;
            float2 v0 = {acc[mt][nt][0] + bx, acc[mt][nt][1] + by};
            float2 v1 = {acc[mt][nt][2] + bx, acc[mt][nt][3] + by};
            *(float2*)&obase[(size_t)s * HD]       = v0;
            *(float2*)&obase[(size_t)(s + 8) * HD] = v1;
        }
    }
}

__global__ __launch_bounds__(256, 1) void out_mma(
    const float* __restrict__ Wo, const float* __restrict__ bo,
    const float* __restrict__ mask, float* __restrict__ out)
{
    extern __shared__ uint32_t dsm[];
    uint32_t* Ap = dsm;
    uint32_t* Bp = dsm + 128 * DST;

    const int t    = threadIdx.x;
    const int lane = t & 31;
    const int w    = t >> 5;
    const int wm   = w >> 2;
    const int wn   = w & 3;
    const int g    = lane >> 2;
    const int qd   = lane & 3;
    const int m0   = blockIdx.x * 128;
    const int n0   = blockIdx.y * 256;

    float acc[4][8][4];
#pragma unroll
    for (int mt = 0; mt < 4; mt++)
#pragma unroll
        for (int nt = 0; nt < 8; nt++)
#pragma unroll
            for (int e = 0; e < 4; e++) acc[mt][nt][e] = 0.f;

    dense_gemm_body<1>(g_ln, Wo, Ap, Bp, acc, m0, n0);

#pragma unroll
    for (int nt = 0; nt < 8; nt++) {
        int col = n0 + wn * 64 + nt * 8 + qd * 2;
        float bx = bo[col], by = bo[col + 1];
#pragma unroll
        for (int mt = 0; mt < 4; mt++) {
            int row = m0 + wm * 64 + mt * 16 + g;
            float mk0 = mask[row], mk1 = mask[row + 8];
            float v0 = acc[mt][nt][0] + bx;
            float v1 = acc[mt][nt][1] + by;
            float v2 = acc[mt][nt][2] + bx;
            float v3 = acc[mt][nt][3] + by;
            v0 = (v0 >= 0.f ? v0 : 0.01f * v0) * mk0;
            v1 = (v1 >= 0.f ? v1 : 0.01f * v1) * mk0;
            v2 = (v2 >= 0.f ? v2 : 0.01f * v2) * mk1;
            v3 = (v3 >= 0.f ? v3 : 0.01f * v3) * mk1;
            float2 u0 = {v0, v1};
            float2 u1 = {v2, v3};
            *(float2*)&out[(size_t)row * DD + col]       = u0;
            *(float2*)&out[(size_t)(row + 8) * DD + col] = u1;
        }
    }
}

// =========================================================================
// Flash attention: grid=(S/128, B*H), 256 thr (8 warps), 16 q-rows/warp.
// Plain-layout smem: Q/P stride 68, K stride 68, V stride 72 (k-major frags).
// =========================================================================
#define QST 68
#define VST 72
#define QP_W (128*QST)
#define KP_W (64*QST)
#define VP_W (64*VST)
#define PP_W (128*QST)
#define ATT_SMEM_BYTES ((QP_W + KP_W + VP_W + PP_W + 64) * 4)   // 105728

__global__ __launch_bounds__(256, 1) void attn_mma(const float* __restrict__ mask)
{
    extern __shared__ uint32_t smw[];
    uint32_t* Qp = smw;
    uint32_t* Kp = Qp + QP_W;
    uint32_t* Vp = Kp + KP_W;
    uint32_t* Pp = Vp + VP_W;
    float*    Ms = (float*)(Pp + PP_W);

    const int t    = threadIdx.x;
    const int lane = t & 31;
    const int wq   = t >> 5;            // warp -> 16 q-rows
    const int g    = lane >> 2;
    const int qd   = lane & 3;

    const int q0 = blockIdx.x * 128;
    const int bh = blockIdx.y;
    const int b  = bh >> 4;
    const int h  = bh & 15;

    const float* Qb = g_Q + ((size_t)bh * SS + q0) * HD;
    const float* Kb = g_K + (size_t)bh * SS * HD;
    const float* Vb = g_V + (size_t)bh * SS * HD;
    const float* mb = mask + (size_t)b * SS;

    // ---- stage Q tile (128x64), plain layout, tf32-rounded ----
#pragma unroll
    for (int i = 0; i < 8; i++) {
        int idx = t + i * 256;              // 2048 float4
        int row = idx >> 4, kc = idx & 15;
        float4 v = *(const float4*)&Qb[(size_t)row * HD + kc * 4];
        uint4 u = {f2tf(v.x), f2tf(v.y), f2tf(v.z), f2tf(v.w)};
        *(uint4*)&Qp[row * QST + kc * 4] = u;
    }

    float mi[2] = {-1e30f, -1e30f};
    float li[2] = {0.f, 0.f};
    float o[8][4];
#pragma unroll
    for (int nt = 0; nt < 8; nt++)
#pragma unroll
        for (int e = 0; e < 4; e++) o[nt][e] = 0.f;

    const int arow = (wq * 16 + g) * QST;   // A-frag row base (Q and P)

    for (int j = 0; j < SS / 64; j++) {
        const int kv0 = j * 64;
        __syncthreads();
        // ---- stage K (64x64) and V (64x64) ----
#pragma unroll
        for (int i = 0; i < 4; i++) {
            int idx = t + i * 256;          // 1024 float4
            int row = idx >> 4, kc = idx & 15;
            float4 vk = *(const float4*)&Kb[(size_t)(kv0 + row) * HD + kc * 4];
            uint4 uk = {f2tf(vk.x), f2tf(vk.y), f2tf(vk.z), f2tf(vk.w)};
            *(uint4*)&Kp[row * QST + kc * 4] = uk;
            float4 vv = *(const float4*)&Vb[(size_t)(kv0 + row) * HD + kc * 4];
            uint4 uv = {f2tf(vv.x), f2tf(vv.y), f2tf(vv.z), f2tf(vv.w)};
            *(uint4*)&Vp[row * VST + kc * 4] = uv;
        }
        if (t < 64) Ms[t] = mb[kv0 + t];
        __syncthreads();

        // ---- S = Q K^T ----
        float s[8][4];
#pragma unroll
        for (int nt = 0; nt < 8; nt++)
#pragma unroll
            for (int e = 0; e < 4; e++) s[nt][e] = 0.f;

#pragma unroll
        for (int kt = 0; kt < 8; kt++) {
            uint32_t a[4];
            int p = arow + kt * 8 + qd;
            a[0] = Qp[p];
            a[1] = Qp[p + 8 * QST];
            a[2] = Qp[p + 4];
            a[3] = Qp[p + 8 * QST + 4];
            const int bb = g * QST + kt * 8 + qd;
#pragma unroll
            for (int nt = 0; nt < 8; nt++) {
                uint32_t bf[2];
                int q = bb + nt * 8 * QST;
                bf[0] = Kp[q];
                bf[1] = Kp[q + 4];
                mma8(s[nt], a, bf);
            }
        }

        // ---- scale + mask + online softmax ----
        float mx0 = -1e30f, mx1 = -1e30f;
#pragma unroll
        for (int nt = 0; nt < 8; nt++) {
#pragma unroll
            for (int e = 0; e < 2; e++) {
                int col = nt * 8 + qd * 2 + e;
                float madd = (1.0f - Ms[col]) * -10000.0f;
                s[nt][e]     = s[nt][e]     * 0.125f + madd;
                s[nt][2 + e] = s[nt][2 + e] * 0.125f + madd;
                mx0 = fmaxf(mx0, s[nt][e]);
                mx1 = fmaxf(mx1, s[nt][2 + e]);
            }
        }
        mx0 = fmaxf(mx0, __shfl_xor_sync(0xffffffffu, mx0, 1));
        mx0 = fmaxf(mx0, __shfl_xor_sync(0xffffffffu, mx0, 2));
        mx1 = fmaxf(mx1, __shfl_xor_sync(0xffffffffu, mx1, 1));
        mx1 = fmaxf(mx1, __shfl_xor_sync(0xffffffffu, mx1, 2));

        float mn0 = fmaxf(mi[0], mx0), mn1 = fmaxf(mi[1], mx1);
        float c0 = __expf(mi[0] - mn0), c1 = __expf(mi[1] - mn1);
        mi[0] = mn0; mi[1] = mn1;

        float rs0 = 0.f, rs1 = 0.f;
#pragma unroll
        for (int nt = 0; nt < 8; nt++) {
#pragma unroll
            for (int e = 0; e < 2; e++) {
                s[nt][e]     = __expf(s[nt][e]     - mn0);
                s[nt][2 + e] = __expf(s[nt][2 + e] - mn1);
                rs0 += s[nt][e];
                rs1 += s[nt][2 + e];
            }
        }
        rs0 += __shfl_xor_sync(0xffffffffu, rs0, 1);
        rs0 += __shfl_xor_sync(0xffffffffu, rs0, 2);
        rs1 += __shfl_xor_sync(0xffffffffu, rs1, 1);
        rs1 += __shfl_xor_sync(0xffffffffu, rs1, 2);
        li[0] = li[0] * c0 + rs0;
        li[1] = li[1] * c1 + rs1;
#pragma unroll
        for (int nt = 0; nt < 8; nt++) {
            o[nt][0] *= c0; o[nt][1] *= c0;
            o[nt][2] *= c1; o[nt][3] *= c1;
        }

        // ---- stage P (warp-private rows), plain layout ----
#pragma unroll
        for (int nt = 0; nt < 8; nt++) {
            int pcol = nt * 8 + qd * 2;
            uint2 u0 = {f2tf(s[nt][0]), f2tf(s[nt][1])};
            uint2 u1 = {f2tf(s[nt][2]), f2tf(s[nt][3])};
            *(uint2*)&Pp[arow + pcol]            = u0;
            *(uint2*)&Pp[arow + 8 * QST + pcol]  = u1;
        }
        __syncwarp();

        // ---- O += P @ V  (V k-major B-frags: bank 8qd+g, conflict-free) ----
#pragma unroll
        for (int kt = 0; kt < 8; kt++) {
            uint32_t a[4];
            int p = arow + kt * 8 + qd;
            a[0] = Pp[p];
            a[1] = Pp[p + 8 * QST];
            a[2] = Pp[p + 4];
            a[3] = Pp[p + 8 * QST + 4];
            const int vb0 = (kt * 8 + qd) * VST + g;
            const int vb1 = (kt * 8 + qd + 4) * VST + g;
#pragma unroll
            for (int nt = 0; nt < 8; nt++) {
                uint32_t bf[2];
                bf[0] = Vp[vb0 + nt * 8];
                bf[1] = Vp[vb1 + nt * 8];
                mma8(o[nt], a, bf);
            }
        }
        __syncwarp();
    }

    // ---- epilogue: normalize, write ctx[b][s][h*64+d] ----
    float inv0 = 1.0f / li[0], inv1 = 1.0f / li[1];
    int row0 = q0 + wq * 16 + g;
    float* cb = g_ctx + (size_t)(b * SS) * DD + h * HD;
#pragma unroll
    for (int nt = 0; nt < 8; nt++) {
        int d = nt * 8 + qd * 2;
        float2 u0 = {o[nt][0] * inv0, o[nt][1] * inv0};
        float2 u1 = {o[nt][2] * inv1, o[nt][3] * inv1};
        *(float2*)&cb[(size_t)row0 * DD + d]       = u0;
        *(float2*)&cb[(size_t)(row0 + 8) * DD + d] = u1;
    }
}

// =========================================================================
// Kernel 3: residual add + LayerNorm, one block per row
// =========================================================================
__device__ __forceinline__ float block_reduce_sum(float v, float* sred)
{
    int t = threadIdx.x;
#pragma unroll
    for (int o = 16; o > 0; o >>= 1) v += __shfl_xor_sync(0xffffffffu, v, o);
    if ((t & 31) == 0) sred[t >> 5] = v;
    __syncthreads();
    if (t < 32) {
        float x = (t < 8) ? sred[t] : 0.f;
#pragma unroll
        for (int o = 4; o > 0; o >>= 1) x += __shfl_xor_sync(0xffffffffu, x, o);
        if (t == 0) sred[0] = x;
    }
    __syncthreads();
    float r = sred[0];
    __syncthreads();
    return r;
}

__global__ __launch_bounds__(256) void ln_kernel(
    const float* __restrict__ resid,
    const float* __restrict__ gamma, const float* __restrict__ beta)
{
    __shared__ float sred[8];
    const int row = blockIdx.x;
    const int t = threadIdx.x;

    float4 c4 = *(const float4*)&g_ctx[(size_t)row * DD + t * 4];
    float4 r4 = *(const float4*)&resid[(size_t)row * DD + t * 4];
    float x0 = c4.x + r4.x, x1 = c4.y + r4.y, x2 = c4.z + r4.z, x3 = c4.w + r4.w;

    float mu = block_reduce_sum(x0 + x1 + x2 + x3, sred) * (1.0f / DD);
    float d0 = x0 - mu, d1 = x1 - mu, d2 = x2 - mu, d3 = x3 - mu;
    float var = block_reduce_sum(d0 * d0 + d1 * d1 + d2 * d2 + d3 * d3, sred) * (1.0f / DD);
    float rstd = rsqrtf(var + 1e-5f);

    float4 g4 = *(const float4*)&gamma[t * 4];
    float4 b4 = *(const float4*)&beta[t * 4];
    float4 res;
    res.x = d0 * rstd * g4.x + b4.x;
    res.y = d1 * rstd * g4.y + b4.y;
    res.z = d2 * rstd * g4.z + b4.z;
    res.w = d3 * rstd * g4.w + b4.w;
    *(float4*)&g_ln[(size_t)row * DD + t * 4] = res;
}

// =========================================================================
// launch
// =========================================================================
extern "C" void kernel_launch(void* const* d_in, const int* in_sizes, int n_in,
                              void* d_out, int out_size)
{
    const float* inputs = (const float*)d_in[0];
    const float* mask   = (const float*)d_in[1];
    const float* Wq = (const float*)d_in[2];
    const float* bq = (const float*)d_in[3];
    const float* Wk = (const float*)d_in[4];
    const float* bk = (const float*)d_in[5];
    const float* Wv = (const float*)d_in[6];
    const float* bv = (const float*)d_in[7];
    const float* Wo = (const float*)d_in[8];
    const float* bo = (const float*)d_in[9];
    const float* ln_g = (const float*)d_in[10];
    const float* ln_b = (const float*)d_in[11];
    float* out = (float*)d_out;

    cudaFuncSetAttribute(qkv_mma, cudaFuncAttributeMaxDynamicSharedMemorySize, DSM_BYTES);
    cudaFuncSetAttribute(out_mma, cudaFuncAttributeMaxDynamicSharedMemorySize, DSM_BYTES);
    cudaFuncSetAttribute(attn_mma, cudaFuncAttributeMaxDynamicSharedMemorySize, ATT_SMEM_BYTES);

    qkv_mma<<<dim3(NTOK / 128, DD / 256, 3), 256, DSM_BYTES>>>(inputs, Wq, bq, Wk, bk, Wv, bv);
    attn_mma<<<dim3(SS / 128, BB * HH), 256, ATT_SMEM_BYTES>>>(mask);
    ln_kernel<<<NTOK, 256>>>(inputs, ln_g, ln_b);
    out_mma<<<dim3(NTOK / 128, DD / 256), 256, DSM_BYTES>>>(Wo, bo, mask, out);
}

// round 6
// speedup vs baseline: 1.1095x; 1.1095x over previous
#include <cuda_runtime.h>
#include <cstdint>

#define BB 4
#define SS 2048
#define DD 1024
#define HH 16
#define HD 64
#define NTOK (BB*SS)          // 8192

// ---------------- scratch (device globals; no allocation) ----------------
__device__ float g_Q[(size_t)BB*HH*SS*HD];     // [B,H,S,HD]
__device__ float g_K[(size_t)BB*HH*SS*HD];
__device__ float g_V[(size_t)BB*HH*SS*HD];
__device__ float g_ctx[(size_t)NTOK*DD];       // [B,S,D]
__device__ float g_ln[(size_t)NTOK*DD];        // [B,S,D]

// ---------------- tf32 mma helpers ----------------
__device__ __forceinline__ uint32_t f2tf(float x) {
    uint32_t u; asm("cvt.rna.tf32.f32 %0, %1;" : "=r"(u) : "f"(x)); return u;
}
__device__ __forceinline__ void mma8(float d[4], const uint32_t a[4], const uint32_t b[2]) {
    asm("mma.sync.aligned.m16n8k8.row.col.f32.tf32.tf32.f32 "
        "{%0,%1,%2,%3}, {%4,%5,%6,%7}, {%8,%9}, {%0,%1,%2,%3};"
        : "+f"(d[0]), "+f"(d[1]), "+f"(d[2]), "+f"(d[3])
        : "r"(a[0]), "r"(a[1]), "r"(a[2]), "r"(a[3]), "r"(b[0]), "r"(b[1]));
}

// =========================================================================
// Dense GEMM: CTA 128x128x32, 256 thr (8 warps = 2m x 4n), warp 64x32.
// Plain-layout smem (stride 36 words -> frag LDS bank = 4g+qd = lane,
// conflict-free), register-prefetch + double-buffered smem pipeline.
// =========================================================================
#define DST 36
#define DBUF_W (128*DST)                  // words per tensor per stage
#define DSM_BYTES (4*DBUF_W*4)            // A0,B0,A1,B1 = 73728 B

__device__ __forceinline__ void dense_gemm_body(
    const float* __restrict__ Asrc, const float* __restrict__ W,
    uint32_t* dsm, float acc[4][4][4], int m0, int n0)
{
    const int t    = threadIdx.x;
    const int lane = t & 31;
    const int w    = t >> 5;
    const int wm   = w >> 2;        // 0..1
    const int wn   = w & 3;         // 0..3
    const int g    = lane >> 2;
    const int qd   = lane & 3;

    const int srow = t >> 3;        // staging row base 0..31
    const int skc  = t & 7;         // staging float4 chunk along k
    const float* aptr = Asrc + (size_t)(m0 + srow) * DD + skc * 4;
    const float* bptr = W    + (size_t)(n0 + srow) * DD + skc * 4;

    float4 ra[4], rb[4];
    // prologue: load k-tile 0
#pragma unroll
    for (int i = 0; i < 4; i++) {
        ra[i] = *(const float4*)(aptr + (size_t)i * 32 * DD);
        rb[i] = *(const float4*)(bptr + (size_t)i * 32 * DD);
    }
    {
        uint32_t* Ap = dsm;
        uint32_t* Bp = dsm + DBUF_W;
#pragma unroll
        for (int i = 0; i < 4; i++) {
            uint4 ua = {f2tf(ra[i].x), f2tf(ra[i].y), f2tf(ra[i].z), f2tf(ra[i].w)};
            *(uint4*)&Ap[(srow + i * 32) * DST + skc * 4] = ua;
            uint4 ub = {f2tf(rb[i].x), f2tf(rb[i].y), f2tf(rb[i].z), f2tf(rb[i].w)};
            *(uint4*)&Bp[(srow + i * 32) * DST + skc * 4] = ub;
        }
    }
    __syncthreads();

    for (int k0 = 0; k0 < DD; k0 += 32) {
        const int st = (k0 >> 5) & 1;
        uint32_t* Ac = dsm + (st ? 2 * DBUF_W : 0);
        uint32_t* Bc = Ac + DBUF_W;
        const bool nxt = (k0 + 32) < DD;

        // issue next tile's global loads first (latency hidden by mma below)
        if (nxt) {
#pragma unroll
            for (int i = 0; i < 4; i++) {
                ra[i] = *(const float4*)(aptr + (k0 + 32) + (size_t)i * 32 * DD);
                rb[i] = *(const float4*)(bptr + (k0 + 32) + (size_t)i * 32 * DD);
            }
        }

        // compute from current buffers
#pragma unroll
        for (int kt = 0; kt < 4; kt++) {
            uint32_t a[4][4];
            const int ab = (wm * 64 + g) * DST + kt * 8 + qd;
#pragma unroll
            for (int mt = 0; mt < 4; mt++) {
                int p = ab + mt * 16 * DST;
                a[mt][0] = Ac[p];
                a[mt][1] = Ac[p + 8 * DST];
                a[mt][2] = Ac[p + 4];
                a[mt][3] = Ac[p + 8 * DST + 4];
            }
            const int bb = (wn * 32 + g) * DST + kt * 8 + qd;
#pragma unroll
            for (int nt = 0; nt < 4; nt++) {
                uint32_t b2[2];
                int p = bb + nt * 8 * DST;
                b2[0] = Bc[p];
                b2[1] = Bc[p + 4];
#pragma unroll
                for (int mt = 0; mt < 4; mt++)
                    mma8(acc[mt][nt], a[mt], b2);
            }
        }

        // stage next tile into the other buffers
        if (nxt) {
            uint32_t* An = dsm + (st ? 0 : 2 * DBUF_W);
            uint32_t* Bn = An + DBUF_W;
#pragma unroll
            for (int i = 0; i < 4; i++) {
                uint4 ua = {f2tf(ra[i].x), f2tf(ra[i].y), f2tf(ra[i].z), f2tf(ra[i].w)};
                *(uint4*)&An[(srow + i * 32) * DST + skc * 4] = ua;
                uint4 ub = {f2tf(rb[i].x), f2tf(rb[i].y), f2tf(rb[i].z), f2tf(rb[i].w)};
                *(uint4*)&Bn[(srow + i * 32) * DST + skc * 4] = ub;
            }
        }
        __syncthreads();
    }
}

__global__ __launch_bounds__(256, 2) void qkv_mma(
    const float* __restrict__ X,
    const float* __restrict__ Wq, const float* __restrict__ bq,
    const float* __restrict__ Wk, const float* __restrict__ bk,
    const float* __restrict__ Wv, const float* __restrict__ bv)
{
    const float* W; const float* bias; float* out;
    if (blockIdx.z == 0)      { W = Wq; bias = bq; out = g_Q; }
    else if (blockIdx.z == 1) { W = Wk; bias = bk; out = g_K; }
    else                      { W = Wv; bias = bv; out = g_V; }

    extern __shared__ uint32_t dsm[];

    const int t    = threadIdx.x;
    const int lane = t & 31;
    const int w    = t >> 5;
    const int wm   = w >> 2;
    const int wn   = w & 3;
    const int g    = lane >> 2;
    const int qd   = lane & 3;
    const int m0   = blockIdx.x * 128;
    const int n0   = blockIdx.y * 128;

    float acc[4][4][4];
#pragma unroll
    for (int mt = 0; mt < 4; mt++)
#pragma unroll
        for (int nt = 0; nt < 4; nt++)
#pragma unroll
            for (int e = 0; e < 4; e++) acc[mt][nt][e] = 0.f;

    dense_gemm_body(X, W, dsm, acc, m0, n0);

    // epilogue: bias add, scatter to [B,H,S,HD] (32-col warp tile never
    // straddles a 64-wide head)
    const int bidx  = m0 >> 11;
    const int sbase = m0 & (SS - 1);
#pragma unroll
    for (int nt = 0; nt < 4; nt++) {
        int col = n0 + wn * 32 + nt * 8 + qd * 2;
        int h = col >> 6, d = col & 63;
        float bx = bias[col], by = bias[col + 1];
        float* obase = out + ((size_t)(bidx * HH + h) * SS) * HD + d;
#pragma unroll
        for (int mt = 0; mt < 4; mt++) {
            int s = sbase + wm * 64 + mt * 16 + g;
            float2 v0 = {acc[mt][nt][0] + bx, acc[mt][nt][1] + by};
            float2 v1 = {acc[mt][nt][2] + bx, acc[mt][nt][3] + by};
            *(float2*)&obase[(size_t)s * HD]       = v0;
            *(float2*)&obase[(size_t)(s + 8) * HD] = v1;
        }
    }
}

__global__ __launch_bounds__(256, 2) void out_mma(
    const float* __restrict__ Wo, const float* __restrict__ bo,
    const float* __restrict__ mask, float* __restrict__ out)
{
    extern __shared__ uint32_t dsm[];

    const int t    = threadIdx.x;
    const int lane = t & 31;
    const int w    = t >> 5;
    const int wm   = w >> 2;
    const int wn   = w & 3;
    const int g    = lane >> 2;
    const int qd   = lane & 3;
    const int m0   = blockIdx.x * 128;
    const int n0   = blockIdx.y * 128;

    float acc[4][4][4];
#pragma unroll
    for (int mt = 0; mt < 4; mt++)
#pragma unroll
        for (int nt = 0; nt < 4; nt++)
#pragma unroll
            for (int e = 0; e < 4; e++) acc[mt][nt][e] = 0.f;

    dense_gemm_body(g_ln, Wo, dsm, acc, m0, n0);

#pragma unroll
    for (int nt = 0; nt < 4; nt++) {
        int col = n0 + wn * 32 + nt * 8 + qd * 2;
        float bx = bo[col], by = bo[col + 1];
#pragma unroll
        for (int mt = 0; mt < 4; mt++) {
            int row = m0 + wm * 64 + mt * 16 + g;
            float mk0 = mask[row], mk1 = mask[row + 8];
            float v0 = acc[mt][nt][0] + bx;
            float v1 = acc[mt][nt][1] + by;
            float v2 = acc[mt][nt][2] + bx;
            float v3 = acc[mt][nt][3] + by;
            v0 = (v0 >= 0.f ? v0 : 0.01f * v0) * mk0;
            v1 = (v1 >= 0.f ? v1 : 0.01f * v1) * mk0;
            v2 = (v2 >= 0.f ? v2 : 0.01f * v2) * mk1;
            v3 = (v3 >= 0.f ? v3 : 0.01f * v3) * mk1;
            float2 u0 = {v0, v1};
            float2 u1 = {v2, v3};
            *(float2*)&out[(size_t)row * DD + col]       = u0;
            *(float2*)&out[(size_t)(row + 8) * DD + col] = u1;
        }
    }
}

// =========================================================================
// Flash attention: grid=(S/128, B*H), 256 thr (8 warps), 16 q-rows/warp.
// Plain-layout smem: Q/P stride 68, K stride 68, V stride 72 (k-major frags).
// (unchanged from round-5 passing version)
// =========================================================================
#define QST 68
#define VST 72
#define QP_W (128*QST)
#define KP_W (64*QST)
#define VP_W (64*VST)
#define PP_W (128*QST)
#define ATT_SMEM_BYTES ((QP_W + KP_W + VP_W + PP_W + 64) * 4)   // 105728

__global__ __launch_bounds__(256, 1) void attn_mma(const float* __restrict__ mask)
{
    extern __shared__ uint32_t smw[];
    uint32_t* Qp = smw;
    uint32_t* Kp = Qp + QP_W;
    uint32_t* Vp = Kp + KP_W;
    uint32_t* Pp = Vp + VP_W;
    float*    Ms = (float*)(Pp + PP_W);

    const int t    = threadIdx.x;
    const int lane = t & 31;
    const int wq   = t >> 5;            // warp -> 16 q-rows
    const int g    = lane >> 2;
    const int qd   = lane & 3;

    const int q0 = blockIdx.x * 128;
    const int bh = blockIdx.y;
    const int b  = bh >> 4;
    const int h  = bh & 15;

    const float* Qb = g_Q + ((size_t)bh * SS + q0) * HD;
    const float* Kb = g_K + (size_t)bh * SS * HD;
    const float* Vb = g_V + (size_t)bh * SS * HD;
    const float* mb = mask + (size_t)b * SS;

    // ---- stage Q tile (128x64), plain layout, tf32-rounded ----
#pragma unroll
    for (int i = 0; i < 8; i++) {
        int idx = t + i * 256;              // 2048 float4
        int row = idx >> 4, kc = idx & 15;
        float4 v = *(const float4*)&Qb[(size_t)row * HD + kc * 4];
        uint4 u = {f2tf(v.x), f2tf(v.y), f2tf(v.z), f2tf(v.w)};
        *(uint4*)&Qp[row * QST + kc * 4] = u;
    }

    float mi[2] = {-1e30f, -1e30f};
    float li[2] = {0.f, 0.f};
    float o[8][4];
#pragma unroll
    for (int nt = 0; nt < 8; nt++)
#pragma unroll
        for (int e = 0; e < 4; e++) o[nt][e] = 0.f;

    const int arow = (wq * 16 + g) * QST;   // A-frag row base (Q and P)

    for (int j = 0; j < SS / 64; j++) {
        const int kv0 = j * 64;
        __syncthreads();
        // ---- stage K (64x64) and V (64x64) ----
#pragma unroll
        for (int i = 0; i < 4; i++) {
            int idx = t + i * 256;          // 1024 float4
            int row = idx >> 4, kc = idx & 15;
            float4 vk = *(const float4*)&Kb[(size_t)(kv0 + row) * HD + kc * 4];
            uint4 uk = {f2tf(vk.x), f2tf(vk.y), f2tf(vk.z), f2tf(vk.w)};
            *(uint4*)&Kp[row * QST + kc * 4] = uk;
            float4 vv = *(const float4*)&Vb[(size_t)(kv0 + row) * HD + kc * 4];
            uint4 uv = {f2tf(vv.x), f2tf(vv.y), f2tf(vv.z), f2tf(vv.w)};
            *(uint4*)&Vp[row * VST + kc * 4] = uv;
        }
        if (t < 64) Ms[t] = mb[kv0 + t];
        __syncthreads();

        // ---- S = Q K^T ----
        float s[8][4];
#pragma unroll
        for (int nt = 0; nt < 8; nt++)
#pragma unroll
            for (int e = 0; e < 4; e++) s[nt][e] = 0.f;

#pragma unroll
        for (int kt = 0; kt < 8; kt++) {
            uint32_t a[4];
            int p = arow + kt * 8 + qd;
            a[0] = Qp[p];
            a[1] = Qp[p + 8 * QST];
            a[2] = Qp[p + 4];
            a[3] = Qp[p + 8 * QST + 4];
            const int bb = g * QST + kt * 8 + qd;
#pragma unroll
            for (int nt = 0; nt < 8; nt++) {
                uint32_t bf[2];
                int q = bb + nt * 8 * QST;
                bf[0] = Kp[q];
                bf[1] = Kp[q + 4];
                mma8(s[nt], a, bf);
            }
        }

        // ---- scale + mask + online softmax ----
        float mx0 = -1e30f, mx1 = -1e30f;
#pragma unroll
        for (int nt = 0; nt < 8; nt++) {
#pragma unroll
            for (int e = 0; e < 2; e++) {
                int col = nt * 8 + qd * 2 + e;
                float madd = (1.0f - Ms[col]) * -10000.0f;
                s[nt][e]     = s[nt][e]     * 0.125f + madd;
                s[nt][2 + e] = s[nt][2 + e] * 0.125f + madd;
                mx0 = fmaxf(mx0, s[nt][e]);
                mx1 = fmaxf(mx1, s[nt][2 + e]);
            }
        }
        mx0 = fmaxf(mx0, __shfl_xor_sync(0xffffffffu, mx0, 1));
        mx0 = fmaxf(mx0, __shfl_xor_sync(0xffffffffu, mx0, 2));
        mx1 = fmaxf(mx1, __shfl_xor_sync(0xffffffffu, mx1, 1));
        mx1 = fmaxf(mx1, __shfl_xor_sync(0xffffffffu, mx1, 2));

        float mn0 = fmaxf(mi[0], mx0), mn1 = fmaxf(mi[1], mx1);
        float c0 = __expf(mi[0] - mn0), c1 = __expf(mi[1] - mn1);
        mi[0] = mn0; mi[1] = mn1;

        float rs0 = 0.f, rs1 = 0.f;
#pragma unroll
        for (int nt = 0; nt < 8; nt++) {
#pragma unroll
            for (int e = 0; e < 2; e++) {
                s[nt][e]     = __expf(s[nt][e]     - mn0);
                s[nt][2 + e] = __expf(s[nt][2 + e] - mn1);
                rs0 += s[nt][e];
                rs1 += s[nt][2 + e];
            }
        }
        rs0 += __shfl_xor_sync(0xffffffffu, rs0, 1);
        rs0 += __shfl_xor_sync(0xffffffffu, rs0, 2);
        rs1 += __shfl_xor_sync(0xffffffffu, rs1, 1);
        rs1 += __shfl_xor_sync(0xffffffffu, rs1, 2);
        li[0] = li[0] * c0 + rs0;
        li[1] = li[1] * c1 + rs1;
#pragma unroll
        for (int nt = 0; nt < 8; nt++) {
            o[nt][0] *= c0; o[nt][1] *= c0;
            o[nt][2] *= c1; o[nt][3] *= c1;
        }

        // ---- stage P (warp-private rows), plain layout ----
#pragma unroll
        for (int nt = 0; nt < 8; nt++) {
            int pcol = nt * 8 + qd * 2;
            uint2 u0 = {f2tf(s[nt][0]), f2tf(s[nt][1])};
            uint2 u1 = {f2tf(s[nt][2]), f2tf(s[nt][3])};
            *(uint2*)&Pp[arow + pcol]            = u0;
            *(uint2*)&Pp[arow + 8 * QST + pcol]  = u1;
        }
        __syncwarp();

        // ---- O += P @ V  (V k-major B-frags: bank 8qd+g, conflict-free) ----
#pragma unroll
        for (int kt = 0; kt < 8; kt++) {
            uint32_t a[4];
            int p = arow + kt * 8 + qd;
            a[0] = Pp[p];
            a[1] = Pp[p + 8 * QST];
            a[2] = Pp[p + 4];
            a[3] = Pp[p + 8 * QST + 4];
            const int vb0 = (kt * 8 + qd) * VST + g;
            const int vb1 = (kt * 8 + qd + 4) * VST + g;
#pragma unroll
            for (int nt = 0; nt < 8; nt++) {
                uint32_t bf[2];
                bf[0] = Vp[vb0 + nt * 8];
                bf[1] = Vp[vb1 + nt * 8];
                mma8(o[nt], a, bf);
            }
        }
        __syncwarp();
    }

    // ---- epilogue: normalize, write ctx[b][s][h*64+d] ----
    float inv0 = 1.0f / li[0], inv1 = 1.0f / li[1];
    int row0 = q0 + wq * 16 + g;
    float* cb = g_ctx + (size_t)(b * SS) * DD + h * HD;
#pragma unroll
    for (int nt = 0; nt < 8; nt++) {
        int d = nt * 8 + qd * 2;
        float2 u0 = {o[nt][0] * inv0, o[nt][1] * inv0};
        float2 u1 = {o[nt][2] * inv1, o[nt][3] * inv1};
        *(float2*)&cb[(size_t)row0 * DD + d]       = u0;
        *(float2*)&cb[(size_t)(row0 + 8) * DD + d] = u1;
    }
}

// =========================================================================
// Kernel 3: residual add + LayerNorm, one block per row
// =========================================================================
__device__ __forceinline__ float block_reduce_sum(float v, float* sred)
{
    int t = threadIdx.x;
#pragma unroll
    for (int o = 16; o > 0; o >>= 1) v += __shfl_xor_sync(0xffffffffu, v, o);
    if ((t & 31) == 0) sred[t >> 5] = v;
    __syncthreads();
    if (t < 32) {
        float x = (t < 8) ? sred[t] : 0.f;
#pragma unroll
        for (int o = 4; o > 0; o >>= 1) x += __shfl_xor_sync(0xffffffffu, x, o);
        if (t == 0) sred[0] = x;
    }
    __syncthreads();
    float r = sred[0];
    __syncthreads();
    return r;
}

__global__ __launch_bounds__(256) void ln_kernel(
    const float* __restrict__ resid,
    const float* __restrict__ gamma, const float* __restrict__ beta)
{
    __shared__ float sred[8];
    const int row = blockIdx.x;
    const int t = threadIdx.x;

    float4 c4 = *(const float4*)&g_ctx[(size_t)row * DD + t * 4];
    float4 r4 = *(const float4*)&resid[(size_t)row * DD + t * 4];
    float x0 = c4.x + r4.x, x1 = c4.y + r4.y, x2 = c4.z + r4.z, x3 = c4.w + r4.w;

    float mu = block_reduce_sum(x0 + x1 + x2 + x3, sred) * (1.0f / DD);
    float d0 = x0 - mu, d1 = x1 - mu, d2 = x2 - mu, d3 = x3 - mu;
    float var = block_reduce_sum(d0 * d0 + d1 * d1 + d2 * d2 + d3 * d3, sred) * (1.0f / DD);
    float rstd = rsqrtf(var + 1e-5f);

    float4 g4 = *(const float4*)&gamma[t * 4];
    float4 b4 = *(const float4*)&beta[t * 4];
    float4 res;
    res.x = d0 * rstd * g4.x + b4.x;
    res.y = d1 * rstd * g4.y + b4.y;
    res.z = d2 * rstd * g4.z + b4.z;
    res.w = d3 * rstd * g4.w + b4.w;
    *(float4*)&g_ln[(size_t)row * DD + t * 4] = res;
}

// =========================================================================
// launch
// =========================================================================
extern "C" void kernel_launch(void* const* d_in, const int* in_sizes, int n_in,
                              void* d_out, int out_size)
{
    const float* inputs = (const float*)d_in[0];
    const float* mask   = (const float*)d_in[1];
    const float* Wq = (const float*)d_in[2];
    const float* bq = (const float*)d_in[3];
    const float* Wk = (const float*)d_in[4];
    const float* bk = (const float*)d_in[5];
    const float* Wv = (const float*)d_in[6];
    const float* bv = (const float*)d_in[7];
    const float* Wo = (const float*)d_in[8];
    const float* bo = (const float*)d_in[9];
    const float* ln_g = (const float*)d_in[10];
    const float* ln_b = (const float*)d_in[11];
    float* out = (float*)d_out;

    cudaFuncSetAttribute(qkv_mma, cudaFuncAttributeMaxDynamicSharedMemorySize, DSM_BYTES);
    cudaFuncSetAttribute(out_mma, cudaFuncAttributeMaxDynamicSharedMemorySize, DSM_BYTES);
    cudaFuncSetAttribute(attn_mma, cudaFuncAttributeMaxDynamicSharedMemorySize, ATT_SMEM_BYTES);

    qkv_mma<<<dim3(NTOK / 128, DD / 128, 3), 256, DSM_BYTES>>>(inputs, Wq, bq, Wk, bk, Wv, bv);
    attn_mma<<<dim3(SS / 128, BB * HH), 256, ATT_SMEM_BYTES>>>(mask);
    ln_kernel<<<NTOK, 256>>>(inputs, ln_g, ln_b);
    out_mma<<<dim3(NTOK / 128, DD / 128), 256, DSM_BYTES>>>(Wo, bo, mask, out);
}

// round 7
// speedup vs baseline: 1.1836x; 1.0668x over previous
#include <cuda_runtime.h>
#include <cstdint>

#define BB 4
#define SS 2048
#define DD 1024
#define HH 16
#define HD 64
#define NTOK (BB*SS)          // 8192

// ---------------- scratch (device globals; no allocation) ----------------
__device__ float g_Q[(size_t)BB*HH*SS*HD];     // [B,H,S,HD]
__device__ float g_K[(size_t)BB*HH*SS*HD];
__device__ float g_V[(size_t)BB*HH*SS*HD];
__device__ float g_ctx[(size_t)NTOK*DD];       // [B,S,D]
__device__ float g_ln[(size_t)NTOK*DD];        // [B,S,D]

// ---------------- tf32 mma helpers ----------------
__device__ __forceinline__ uint32_t f2tf(float x) {
    uint32_t u; asm("cvt.rna.tf32.f32 %0, %1;" : "=r"(u) : "f"(x)); return u;
}
__device__ __forceinline__ void mma8(float d[4], const uint32_t a[4], const uint32_t b[2]) {
    asm("mma.sync.aligned.m16n8k8.row.col.f32.tf32.tf32.f32 "
        "{%0,%1,%2,%3}, {%4,%5,%6,%7}, {%8,%9}, {%0,%1,%2,%3};"
        : "+f"(d[0]), "+f"(d[1]), "+f"(d[2]), "+f"(d[3])
        : "r"(a[0]), "r"(a[1]), "r"(a[2]), "r"(a[3]), "r"(b[0]), "r"(b[1]));
}

// =========================================================================
// Dense GEMM: CTA 128x128x32, 256 thr (8 warps = 2m x 4n), warp 64x32.
// Plain-layout smem (stride 36 words -> frag LDS bank = 4g+qd = lane,
// conflict-free), register-prefetch + double-buffered smem pipeline.
// (unchanged from round-6 passing version)
// =========================================================================
#define DST 36
#define DBUF_W (128*DST)                  // words per tensor per stage
#define DSM_BYTES (4*DBUF_W*4)            // A0,B0,A1,B1 = 73728 B

__device__ __forceinline__ void dense_gemm_body(
    const float* __restrict__ Asrc, const float* __restrict__ W,
    uint32_t* dsm, float acc[4][4][4], int m0, int n0)
{
    const int t    = threadIdx.x;
    const int lane = t & 31;
    const int w    = t >> 5;
    const int wm   = w >> 2;        // 0..1
    const int wn   = w & 3;         // 0..3
    const int g    = lane >> 2;
    const int qd   = lane & 3;

    const int srow = t >> 3;        // staging row base 0..31
    const int skc  = t & 7;         // staging float4 chunk along k
    const float* aptr = Asrc + (size_t)(m0 + srow) * DD + skc * 4;
    const float* bptr = W    + (size_t)(n0 + srow) * DD + skc * 4;

    float4 ra[4], rb[4];
    // prologue: load k-tile 0
#pragma unroll
    for (int i = 0; i < 4; i++) {
        ra[i] = *(const float4*)(aptr + (size_t)i * 32 * DD);
        rb[i] = *(const float4*)(bptr + (size_t)i * 32 * DD);
    }
    {
        uint32_t* Ap = dsm;
        uint32_t* Bp = dsm + DBUF_W;
#pragma unroll
        for (int i = 0; i < 4; i++) {
            uint4 ua = {f2tf(ra[i].x), f2tf(ra[i].y), f2tf(ra[i].z), f2tf(ra[i].w)};
            *(uint4*)&Ap[(srow + i * 32) * DST + skc * 4] = ua;
            uint4 ub = {f2tf(rb[i].x), f2tf(rb[i].y), f2tf(rb[i].z), f2tf(rb[i].w)};
            *(uint4*)&Bp[(srow + i * 32) * DST + skc * 4] = ub;
        }
    }
    __syncthreads();

    for (int k0 = 0; k0 < DD; k0 += 32) {
        const int st = (k0 >> 5) & 1;
        uint32_t* Ac = dsm + (st ? 2 * DBUF_W : 0);
        uint32_t* Bc = Ac + DBUF_W;
        const bool nxt = (k0 + 32) < DD;

        // issue next tile's global loads first (latency hidden by mma below)
        if (nxt) {
#pragma unroll
            for (int i = 0; i < 4; i++) {
                ra[i] = *(const float4*)(aptr + (k0 + 32) + (size_t)i * 32 * DD);
                rb[i] = *(const float4*)(bptr + (k0 + 32) + (size_t)i * 32 * DD);
            }
        }

        // compute from current buffers
#pragma unroll
        for (int kt = 0; kt < 4; kt++) {
            uint32_t a[4][4];
            const int ab = (wm * 64 + g) * DST + kt * 8 + qd;
#pragma unroll
            for (int mt = 0; mt < 4; mt++) {
                int p = ab + mt * 16 * DST;
                a[mt][0] = Ac[p];
                a[mt][1] = Ac[p + 8 * DST];
                a[mt][2] = Ac[p + 4];
                a[mt][3] = Ac[p + 8 * DST + 4];
            }
            const int bb = (wn * 32 + g) * DST + kt * 8 + qd;
#pragma unroll
            for (int nt = 0; nt < 4; nt++) {
                uint32_t b2[2];
                int p = bb + nt * 8 * DST;
                b2[0] = Bc[p];
                b2[1] = Bc[p + 4];
#pragma unroll
                for (int mt = 0; mt < 4; mt++)
                    mma8(acc[mt][nt], a[mt], b2);
            }
        }

        // stage next tile into the other buffers
        if (nxt) {
            uint32_t* An = dsm + (st ? 0 : 2 * DBUF_W);
            uint32_t* Bn = An + DBUF_W;
#pragma unroll
            for (int i = 0; i < 4; i++) {
                uint4 ua = {f2tf(ra[i].x), f2tf(ra[i].y), f2tf(ra[i].z), f2tf(ra[i].w)};
                *(uint4*)&An[(srow + i * 32) * DST + skc * 4] = ua;
                uint4 ub = {f2tf(rb[i].x), f2tf(rb[i].y), f2tf(rb[i].z), f2tf(rb[i].w)};
                *(uint4*)&Bn[(srow + i * 32) * DST + skc * 4] = ub;
            }
        }
        __syncthreads();
    }
}

__global__ __launch_bounds__(256, 2) void qkv_mma(
    const float* __restrict__ X,
    const float* __restrict__ Wq, const float* __restrict__ bq,
    const float* __restrict__ Wk, const float* __restrict__ bk,
    const float* __restrict__ Wv, const float* __restrict__ bv)
{
    const float* W; const float* bias; float* out;
    if (blockIdx.z == 0)      { W = Wq; bias = bq; out = g_Q; }
    else if (blockIdx.z == 1) { W = Wk; bias = bk; out = g_K; }
    else                      { W = Wv; bias = bv; out = g_V; }

    extern __shared__ uint32_t dsm[];

    const int t    = threadIdx.x;
    const int lane = t & 31;
    const int w    = t >> 5;
    const int wm   = w >> 2;
    const int wn   = w & 3;
    const int g    = lane >> 2;
    const int qd   = lane & 3;
    const int m0   = blockIdx.x * 128;
    const int n0   = blockIdx.y * 128;

    float acc[4][4][4];
#pragma unroll
    for (int mt = 0; mt < 4; mt++)
#pragma unroll
        for (int nt = 0; nt < 4; nt++)
#pragma unroll
            for (int e = 0; e < 4; e++) acc[mt][nt][e] = 0.f;

    dense_gemm_body(X, W, dsm, acc, m0, n0);

    // epilogue: bias add, scatter to [B,H,S,HD] (32-col warp tile never
    // straddles a 64-wide head)
    const int bidx  = m0 >> 11;
    const int sbase = m0 & (SS - 1);
#pragma unroll
    for (int nt = 0; nt < 4; nt++) {
        int col = n0 + wn * 32 + nt * 8 + qd * 2;
        int h = col >> 6, d = col & 63;
        float bx = bias[col], by = bias[col + 1];
        float* obase = out + ((size_t)(bidx * HH + h) * SS) * HD + d;
#pragma unroll
        for (int mt = 0; mt < 4; mt++) {
            int s = sbase + wm * 64 + mt * 16 + g;
            float2 v0 = {acc[mt][nt][0] + bx, acc[mt][nt][1] + by};
            float2 v1 = {acc[mt][nt][2] + bx, acc[mt][nt][3] + by};
            *(float2*)&obase[(size_t)s * HD]       = v0;
            *(float2*)&obase[(size_t)(s + 8) * HD] = v1;
        }
    }
}

__global__ __launch_bounds__(256, 2) void out_mma(
    const float* __restrict__ Wo, const float* __restrict__ bo,
    const float* __restrict__ mask, float* __restrict__ out)
{
    extern __shared__ uint32_t dsm[];

    const int t    = threadIdx.x;
    const int lane = t & 31;
    const int w    = t >> 5;
    const int wm   = w >> 2;
    const int wn   = w & 3;
    const int g    = lane >> 2;
    const int qd   = lane & 3;
    const int m0   = blockIdx.x * 128;
    const int n0   = blockIdx.y * 128;

    float acc[4][4][4];
#pragma unroll
    for (int mt = 0; mt < 4; mt++)
#pragma unroll
        for (int nt = 0; nt < 4; nt++)
#pragma unroll
            for (int e = 0; e < 4; e++) acc[mt][nt][e] = 0.f;

    dense_gemm_body(g_ln, Wo, dsm, acc, m0, n0);

#pragma unroll
    for (int nt = 0; nt < 4; nt++) {
        int col = n0 + wn * 32 + nt * 8 + qd * 2;
        float bx = bo[col], by = bo[col + 1];
#pragma unroll
        for (int mt = 0; mt < 4; mt++) {
            int row = m0 + wm * 64 + mt * 16 + g;
            float mk0 = mask[row], mk1 = mask[row + 8];
            float v0 = acc[mt][nt][0] + bx;
            float v1 = acc[mt][nt][1] + by;
            float v2 = acc[mt][nt][2] + bx;
            float v3 = acc[mt][nt][3] + by;
            v0 = (v0 >= 0.f ? v0 : 0.01f * v0) * mk0;
            v1 = (v1 >= 0.f ? v1 : 0.01f * v1) * mk0;
            v2 = (v2 >= 0.f ? v2 : 0.01f * v2) * mk1;
            v3 = (v3 >= 0.f ? v3 : 0.01f * v3) * mk1;
            float2 u0 = {v0, v1};
            float2 u1 = {v2, v3};
            *(float2*)&out[(size_t)row * DD + col]       = u0;
            *(float2*)&out[(size_t)(row + 8) * DD + col] = u1;
        }
    }
}

// =========================================================================
// Flash attention: grid=(S/128, B*H), 256 thr (8 warps), 16 q-rows/warp.
// Plain-layout smem: Q/P stride 68, K stride 68, V stride 72 (k-major frags).
// NEW: K/V/mask double-buffered with register prefetch; 1 syncthreads/iter.
// =========================================================================
#define QST 68
#define VST 72
#define KBUF_W (64*QST)
#define VBUF_W (64*VST)
// Qp | Kp[2] | Vp[2] | Pp | Ms[2]
#define ATT_SMEM_WORDS (128*QST + 2*KBUF_W + 2*VBUF_W + 128*QST + 2*64)
#define ATT_SMEM_BYTES (ATT_SMEM_WORDS * 4)   // 141824

__global__ __launch_bounds__(256, 1) void attn_mma(const float* __restrict__ mask)
{
    extern __shared__ uint32_t smw[];
    uint32_t* Qp = smw;                          // 128*QST
    uint32_t* Kp = Qp + 128*QST;                 // 2 * KBUF_W
    uint32_t* Vp = Kp + 2*KBUF_W;                // 2 * VBUF_W
    uint32_t* Pp = Vp + 2*VBUF_W;                // 128*QST
    float*    Ms = (float*)(Pp + 128*QST);       // 2 * 64

    const int t    = threadIdx.x;
    const int lane = t & 31;
    const int wq   = t >> 5;            // warp -> 16 q-rows
    const int g    = lane >> 2;
    const int qd   = lane & 3;

    const int q0 = blockIdx.x * 128;
    const int bh = blockIdx.y;
    const int b  = bh >> 4;
    const int h  = bh & 15;

    const float* Qb = g_Q + ((size_t)bh * SS + q0) * HD;
    const float* Kb = g_K + (size_t)bh * SS * HD;
    const float* Vb = g_V + (size_t)bh * SS * HD;
    const float* mb = mask + (size_t)b * SS;

    // staging geometry: 4 float4 per thread per tensor per tile
    const int srow = t >> 4;            // 0..15 (+i*16? no: idx>>4 with idx=t+i*256)
    const int skc  = t & 15;

    // ---- stage Q tile (128x64), plain layout, tf32-rounded ----
#pragma unroll
    for (int i = 0; i < 8; i++) {
        int idx = t + i * 256;              // 2048 float4
        int row = idx >> 4, kc = idx & 15;
        float4 v = *(const float4*)&Qb[(size_t)row * HD + kc * 4];
        uint4 u = {f2tf(v.x), f2tf(v.y), f2tf(v.z), f2tf(v.w)};
        *(uint4*)&Qp[row * QST + kc * 4] = u;
    }

    float mi[2] = {-1e30f, -1e30f};
    float li[2] = {0.f, 0.f};
    float o[8][4];
#pragma unroll
    for (int nt = 0; nt < 8; nt++)
#pragma unroll
        for (int e = 0; e < 4; e++) o[nt][e] = 0.f;

    const int arow = (wq * 16 + g) * QST;   // A-frag row base (Q and P)

    // ---- prologue: prefetch + stage KV tile 0 into buffer 0 ----
    float4 rk[4], rv[4]; float rm = 0.f;
#pragma unroll
    for (int i = 0; i < 4; i++) {
        int row = srow + i * 16;
        rk[i] = *(const float4*)&Kb[(size_t)row * HD + skc * 4];
        rv[i] = *(const float4*)&Vb[(size_t)row * HD + skc * 4];
    }
    if (t < 64) rm = mb[t];
#pragma unroll
    for (int i = 0; i < 4; i++) {
        int row = srow + i * 16;
        uint4 uk = {f2tf(rk[i].x), f2tf(rk[i].y), f2tf(rk[i].z), f2tf(rk[i].w)};
        *(uint4*)&Kp[row * QST + skc * 4] = uk;
        uint4 uv = {f2tf(rv[i].x), f2tf(rv[i].y), f2tf(rv[i].z), f2tf(rv[i].w)};
        *(uint4*)&Vp[row * VST + skc * 4] = uv;
    }
    if (t < 64) Ms[t] = rm;
    __syncthreads();

    for (int j = 0; j < SS / 64; j++) {
        const int buf = j & 1;
        const uint32_t* Kc = Kp + buf * KBUF_W;
        const uint32_t* Vc = Vp + buf * VBUF_W;
        const float*    Mc = Ms + buf * 64;
        const bool nxt = (j + 1) < (SS / 64);

        // ---- issue next tile's global loads (hidden by the mma below) ----
        if (nxt) {
            const int kv0 = (j + 1) * 64;
#pragma unroll
            for (int i = 0; i < 4; i++) {
                int row = kv0 + srow + i * 16;
                rk[i] = *(const float4*)&Kb[(size_t)row * HD + skc * 4];
                rv[i] = *(const float4*)&Vb[(size_t)row * HD + skc * 4];
            }
            if (t < 64) rm = mb[kv0 + t];
        }

        // ---- S = Q K^T ----
        float s[8][4];
#pragma unroll
        for (int nt = 0; nt < 8; nt++)
#pragma unroll
            for (int e = 0; e < 4; e++) s[nt][e] = 0.f;

#pragma unroll
        for (int kt = 0; kt < 8; kt++) {
            uint32_t a[4];
            int p = arow + kt * 8 + qd;
            a[0] = Qp[p];
            a[1] = Qp[p + 8 * QST];
            a[2] = Qp[p + 4];
            a[3] = Qp[p + 8 * QST + 4];
            const int bb = g * QST + kt * 8 + qd;
#pragma unroll
            for (int nt = 0; nt < 8; nt++) {
                uint32_t bf[2];
                int q = bb + nt * 8 * QST;
                bf[0] = Kc[q];
                bf[1] = Kc[q + 4];
                mma8(s[nt], a, bf);
            }
        }

        // ---- scale + mask + online softmax ----
        float mx0 = -1e30f, mx1 = -1e30f;
#pragma unroll
        for (int nt = 0; nt < 8; nt++) {
#pragma unroll
            for (int e = 0; e < 2; e++) {
                int col = nt * 8 + qd * 2 + e;
                float madd = (1.0f - Mc[col]) * -10000.0f;
                s[nt][e]     = s[nt][e]     * 0.125f + madd;
                s[nt][2 + e] = s[nt][2 + e] * 0.125f + madd;
                mx0 = fmaxf(mx0, s[nt][e]);
                mx1 = fmaxf(mx1, s[nt][2 + e]);
            }
        }
        mx0 = fmaxf(mx0, __shfl_xor_sync(0xffffffffu, mx0, 1));
        mx0 = fmaxf(mx0, __shfl_xor_sync(0xffffffffu, mx0, 2));
        mx1 = fmaxf(mx1, __shfl_xor_sync(0xffffffffu, mx1, 1));
        mx1 = fmaxf(mx1, __shfl_xor_sync(0xffffffffu, mx1, 2));

        float mn0 = fmaxf(mi[0], mx0), mn1 = fmaxf(mi[1], mx1);
        float c0 = __expf(mi[0] - mn0), c1 = __expf(mi[1] - mn1);
        mi[0] = mn0; mi[1] = mn1;

        float rs0 = 0.f, rs1 = 0.f;
#pragma unroll
        for (int nt = 0; nt < 8; nt++) {
#pragma unroll
            for (int e = 0; e < 2; e++) {
                s[nt][e]     = __expf(s[nt][e]     - mn0);
                s[nt][2 + e] = __expf(s[nt][2 + e] - mn1);
                rs0 += s[nt][e];
                rs1 += s[nt][2 + e];
            }
        }
        rs0 += __shfl_xor_sync(0xffffffffu, rs0, 1);
        rs0 += __shfl_xor_sync(0xffffffffu, rs0, 2);
        rs1 += __shfl_xor_sync(0xffffffffu, rs1, 1);
        rs1 += __shfl_xor_sync(0xffffffffu, rs1, 2);
        li[0] = li[0] * c0 + rs0;
        li[1] = li[1] * c1 + rs1;
#pragma unroll
        for (int nt = 0; nt < 8; nt++) {
            o[nt][0] *= c0; o[nt][1] *= c0;
            o[nt][2] *= c1; o[nt][3] *= c1;
        }

        // ---- stage P (warp-private rows), plain layout ----
#pragma unroll
        for (int nt = 0; nt < 8; nt++) {
            int pcol = nt * 8 + qd * 2;
            uint2 u0 = {f2tf(s[nt][0]), f2tf(s[nt][1])};
            uint2 u1 = {f2tf(s[nt][2]), f2tf(s[nt][3])};
            *(uint2*)&Pp[arow + pcol]            = u0;
            *(uint2*)&Pp[arow + 8 * QST + pcol]  = u1;
        }
        __syncwarp();

        // ---- O += P @ V  (V k-major B-frags: bank 8qd+g, conflict-free) ----
#pragma unroll
        for (int kt = 0; kt < 8; kt++) {
            uint32_t a[4];
            int p = arow + kt * 8 + qd;
            a[0] = Pp[p];
            a[1] = Pp[p + 8 * QST];
            a[2] = Pp[p + 4];
            a[3] = Pp[p + 8 * QST + 4];
            const int vb0 = (kt * 8 + qd) * VST + g;
            const int vb1 = (kt * 8 + qd + 4) * VST + g;
#pragma unroll
            for (int nt = 0; nt < 8; nt++) {
                uint32_t bf[2];
                bf[0] = Vc[vb0 + nt * 8];
                bf[1] = Vc[vb1 + nt * 8];
                mma8(o[nt], a, bf);
            }
        }
        __syncwarp();

        // ---- stage next tile into the other buffers ----
        // (safe: buf^1 was last read in iter j-1, whose end barrier passed)
        if (nxt) {
            uint32_t* Kn = Kp + (buf ^ 1) * KBUF_W;
            uint32_t* Vn = Vp + (buf ^ 1) * VBUF_W;
#pragma unroll
            for (int i = 0; i < 4; i++) {
                int row = srow + i * 16;
                uint4 uk = {f2tf(rk[i].x), f2tf(rk[i].y), f2tf(rk[i].z), f2tf(rk[i].w)};
                *(uint4*)&Kn[row * QST + skc * 4] = uk;
                uint4 uv = {f2tf(rv[i].x), f2tf(rv[i].y), f2tf(rv[i].z), f2tf(rv[i].w)};
                *(uint4*)&Vn[row * VST + skc * 4] = uv;
            }
            if (t < 64) Ms[(buf ^ 1) * 64 + t] = rm;
        }
        __syncthreads();
    }

    // ---- epilogue: normalize, write ctx[b][s][h*64+d] ----
    float inv0 = 1.0f / li[0], inv1 = 1.0f / li[1];
    int row0 = q0 + wq * 16 + g;
    float* cb = g_ctx + (size_t)(b * SS) * DD + h * HD;
#pragma unroll
    for (int nt = 0; nt < 8; nt++) {
        int d = nt * 8 + qd * 2;
        float2 u0 = {o[nt][0] * inv0, o[nt][1] * inv0};
        float2 u1 = {o[nt][2] * inv1, o[nt][3] * inv1};
        *(float2*)&cb[(size_t)row0 * DD + d]       = u0;
        *(float2*)&cb[(size_t)(row0 + 8) * DD + d] = u1;
    }
}

// =========================================================================
// Kernel 3: residual add + LayerNorm, one block per row
// =========================================================================
__device__ __forceinline__ float block_reduce_sum(float v, float* sred)
{
    int t = threadIdx.x;
#pragma unroll
    for (int o = 16; o > 0; o >>= 1) v += __shfl_xor_sync(0xffffffffu, v, o);
    if ((t & 31) == 0) sred[t >> 5] = v;
    __syncthreads();
    if (t < 32) {
        float x = (t < 8) ? sred[t] : 0.f;
#pragma unroll
        for (int o = 4; o > 0; o >>= 1) x += __shfl_xor_sync(0xffffffffu, x, o);
        if (t == 0) sred[0] = x;
    }
    __syncthreads();
    float r = sred[0];
    __syncthreads();
    return r;
}

__global__ __launch_bounds__(256) void ln_kernel(
    const float* __restrict__ resid,
    const float* __restrict__ gamma, const float* __restrict__ beta)
{
    __shared__ float sred[8];
    const int row = blockIdx.x;
    const int t = threadIdx.x;

    float4 c4 = *(const float4*)&g_ctx[(size_t)row * DD + t * 4];
    float4 r4 = *(const float4*)&resid[(size_t)row * DD + t * 4];
    float x0 = c4.x + r4.x, x1 = c4.y + r4.y, x2 = c4.z + r4.z, x3 = c4.w + r4.w;

    float mu = block_reduce_sum(x0 + x1 + x2 + x3, sred) * (1.0f / DD);
    float d0 = x0 - mu, d1 = x1 - mu, d2 = x2 - mu, d3 = x3 - mu;
    float var = block_reduce_sum(d0 * d0 + d1 * d1 + d2 * d2 + d3 * d3, sred) * (1.0f / DD);
    float rstd = rsqrtf(var + 1e-5f);

    float4 g4 = *(const float4*)&gamma[t * 4];
    float4 b4 = *(const float4*)&beta[t * 4];
    float4 res;
    res.x = d0 * rstd * g4.x + b4.x;
    res.y = d1 * rstd * g4.y + b4.y;
    res.z = d2 * rstd * g4.z + b4.z;
    res.w = d3 * rstd * g4.w + b4.w;
    *(float4*)&g_ln[(size_t)row * DD + t * 4] = res;
}

// =========================================================================
// launch
// =========================================================================
extern "C" void kernel_launch(void* const* d_in, const int* in_sizes, int n_in,
                              void* d_out, int out_size)
{
    const float* inputs = (const float*)d_in[0];
    const float* mask   = (const float*)d_in[1];
    const float* Wq = (const float*)d_in[2];
    const float* bq = (const float*)d_in[3];
    const float* Wk = (const float*)d_in[4];
    const float* bk = (const float*)d_in[5];
    const float* Wv = (const float*)d_in[6];
    const float* bv = (const float*)d_in[7];
    const float* Wo = (const float*)d_in[8];
    const float* bo = (const float*)d_in[9];
    const float* ln_g = (const float*)d_in[10];
    const float* ln_b = (const float*)d_in[11];
    float* out = (float*)d_out;

    cudaFuncSetAttribute(qkv_mma, cudaFuncAttributeMaxDynamicSharedMemorySize, DSM_BYTES);
    cudaFuncSetAttribute(out_mma, cudaFuncAttributeMaxDynamicSharedMemorySize, DSM_BYTES);
    cudaFuncSetAttribute(attn_mma, cudaFuncAttributeMaxDynamicSharedMemorySize, ATT_SMEM_BYTES);

    qkv_mma<<<dim3(NTOK / 128, DD / 128, 3), 256, DSM_BYTES>>>(inputs, Wq, bq, Wk, bk, Wv, bv);
    attn_mma<<<dim3(SS / 128, BB * HH), 256, ATT_SMEM_BYTES>>>(mask);
    ln_kernel<<<NTOK, 256>>>(inputs, ln_g, ln_b);
    out_mma<<<dim3(NTOK / 128, DD / 128), 256, DSM_BYTES>>>(Wo, bo, mask, out);
}

// round 8
// speedup vs baseline: 1.2851x; 1.0857x over previous
#include <cuda_runtime.h>
#include <cstdint>

#define BB 4
#define SS 2048
#define DD 1024
#define HH 16
#define HD 64
#define NTOK (BB*SS)          // 8192

// ---------------- scratch (device globals; no allocation) ----------------
// g_Q/g_K/g_V hold tf32-pre-rounded values (written by qkv epilogue)
__device__ float g_Q[(size_t)BB*HH*SS*HD];     // [B,H,S,HD]
__device__ float g_K[(size_t)BB*HH*SS*HD];
__device__ float g_V[(size_t)BB*HH*SS*HD];
__device__ float g_ctx[(size_t)NTOK*DD];       // [B,S,D]
__device__ float g_ln[(size_t)NTOK*DD];        // [B,S,D]

// ---------------- tf32 mma helpers ----------------
__device__ __forceinline__ uint32_t f2tf(float x) {
    uint32_t u; asm("cvt.rna.tf32.f32 %0, %1;" : "=r"(u) : "f"(x)); return u;
}
__device__ __forceinline__ void mma8(float d[4], const uint32_t a[4], const uint32_t b[2]) {
    asm("mma.sync.aligned.m16n8k8.row.col.f32.tf32.tf32.f32 "
        "{%0,%1,%2,%3}, {%4,%5,%6,%7}, {%8,%9}, {%0,%1,%2,%3};"
        : "+f"(d[0]), "+f"(d[1]), "+f"(d[2]), "+f"(d[3])
        : "r"(a[0]), "r"(a[1]), "r"(a[2]), "r"(a[3]), "r"(b[0]), "r"(b[1]));
}

// =========================================================================
// Dense GEMM: CTA 128x128x32, 256 thr (8 warps = 2m x 4n), warp 64x32.
// (unchanged from round-7 passing version)
// =========================================================================
#define DST 36
#define DBUF_W (128*DST)
#define DSM_BYTES (4*DBUF_W*4)            // 73728 B

__device__ __forceinline__ void dense_gemm_body(
    const float* __restrict__ Asrc, const float* __restrict__ W,
    uint32_t* dsm, float acc[4][4][4], int m0, int n0)
{
    const int t    = threadIdx.x;
    const int lane = t & 31;
    const int w    = t >> 5;
    const int wm   = w >> 2;
    const int wn   = w & 3;
    const int g    = lane >> 2;
    const int qd   = lane & 3;

    const int srow = t >> 3;
    const int skc  = t & 7;
    const float* aptr = Asrc + (size_t)(m0 + srow) * DD + skc * 4;
    const float* bptr = W    + (size_t)(n0 + srow) * DD + skc * 4;

    float4 ra[4], rb[4];
#pragma unroll
    for (int i = 0; i < 4; i++) {
        ra[i] = *(const float4*)(aptr + (size_t)i * 32 * DD);
        rb[i] = *(const float4*)(bptr + (size_t)i * 32 * DD);
    }
    {
        uint32_t* Ap = dsm;
        uint32_t* Bp = dsm + DBUF_W;
#pragma unroll
        for (int i = 0; i < 4; i++) {
            uint4 ua = {f2tf(ra[i].x), f2tf(ra[i].y), f2tf(ra[i].z), f2tf(ra[i].w)};
            *(uint4*)&Ap[(srow + i * 32) * DST + skc * 4] = ua;
            uint4 ub = {f2tf(rb[i].x), f2tf(rb[i].y), f2tf(rb[i].z), f2tf(rb[i].w)};
            *(uint4*)&Bp[(srow + i * 32) * DST + skc * 4] = ub;
        }
    }
    __syncthreads();

    for (int k0 = 0; k0 < DD; k0 += 32) {
        const int st = (k0 >> 5) & 1;
        uint32_t* Ac = dsm + (st ? 2 * DBUF_W : 0);
        uint32_t* Bc = Ac + DBUF_W;
        const bool nxt = (k0 + 32) < DD;

        if (nxt) {
#pragma unroll
            for (int i = 0; i < 4; i++) {
                ra[i] = *(const float4*)(aptr + (k0 + 32) + (size_t)i * 32 * DD);
                rb[i] = *(const float4*)(bptr + (k0 + 32) + (size_t)i * 32 * DD);
            }
        }

#pragma unroll
        for (int kt = 0; kt < 4; kt++) {
            uint32_t a[4][4];
            const int ab = (wm * 64 + g) * DST + kt * 8 + qd;
#pragma unroll
            for (int mt = 0; mt < 4; mt++) {
                int p = ab + mt * 16 * DST;
                a[mt][0] = Ac[p];
                a[mt][1] = Ac[p + 8 * DST];
                a[mt][2] = Ac[p + 4];
                a[mt][3] = Ac[p + 8 * DST + 4];
            }
            const int bb = (wn * 32 + g) * DST + kt * 8 + qd;
#pragma unroll
            for (int nt = 0; nt < 4; nt++) {
                uint32_t b2[2];
                int p = bb + nt * 8 * DST;
                b2[0] = Bc[p];
                b2[1] = Bc[p + 4];
#pragma unroll
                for (int mt = 0; mt < 4; mt++)
                    mma8(acc[mt][nt], a[mt], b2);
            }
        }

        if (nxt) {
            uint32_t* An = dsm + (st ? 0 : 2 * DBUF_W);
            uint32_t* Bn = An + DBUF_W;
#pragma unroll
            for (int i = 0; i < 4; i++) {
                uint4 ua = {f2tf(ra[i].x), f2tf(ra[i].y), f2tf(ra[i].z), f2tf(ra[i].w)};
                *(uint4*)&An[(srow + i * 32) * DST + skc * 4] = ua;
                uint4 ub = {f2tf(rb[i].x), f2tf(rb[i].y), f2tf(rb[i].z), f2tf(rb[i].w)};
                *(uint4*)&Bn[(srow + i * 32) * DST + skc * 4] = ub;
            }
        }
        __syncthreads();
    }
}

__global__ __launch_bounds__(256, 2) void qkv_mma(
    const float* __restrict__ X,
    const float* __restrict__ Wq, const float* __restrict__ bq,
    const float* __restrict__ Wk, const float* __restrict__ bk,
    const float* __restrict__ Wv, const float* __restrict__ bv)
{
    const float* W; const float* bias; float* out;
    if (blockIdx.z == 0)      { W = Wq; bias = bq; out = g_Q; }
    else if (blockIdx.z == 1) { W = Wk; bias = bk; out = g_K; }
    else                      { W = Wv; bias = bv; out = g_V; }

    extern __shared__ uint32_t dsm[];

    const int t    = threadIdx.x;
    const int lane = t & 31;
    const int w    = t >> 5;
    const int wm   = w >> 2;
    const int wn   = w & 3;
    const int g    = lane >> 2;
    const int qd   = lane & 3;
    const int m0   = blockIdx.x * 128;
    const int n0   = blockIdx.y * 128;

    float acc[4][4][4];
#pragma unroll
    for (int mt = 0; mt < 4; mt++)
#pragma unroll
        for (int nt = 0; nt < 4; nt++)
#pragma unroll
            for (int e = 0; e < 4; e++) acc[mt][nt][e] = 0.f;

    dense_gemm_body(X, W, dsm, acc, m0, n0);

    // epilogue: bias add, tf32 pre-round, scatter to [B,H,S,HD]
    const int bidx  = m0 >> 11;
    const int sbase = m0 & (SS - 1);
#pragma unroll
    for (int nt = 0; nt < 4; nt++) {
        int col = n0 + wn * 32 + nt * 8 + qd * 2;
        int h = col >> 6, d = col & 63;
        float bx = bias[col], by = bias[col + 1];
        float* obase = out + ((size_t)(bidx * HH + h) * SS) * HD + d;
#pragma unroll
        for (int mt = 0; mt < 4; mt++) {
            int s = sbase + wm * 64 + mt * 16 + g;
            float2 v0 = {__uint_as_float(f2tf(acc[mt][nt][0] + bx)),
                         __uint_as_float(f2tf(acc[mt][nt][1] + by))};
            float2 v1 = {__uint_as_float(f2tf(acc[mt][nt][2] + bx)),
                         __uint_as_float(f2tf(acc[mt][nt][3] + by))};
            *(float2*)&obase[(size_t)s * HD]       = v0;
            *(float2*)&obase[(size_t)(s + 8) * HD] = v1;
        }
    }
}

__global__ __launch_bounds__(256, 2) void out_mma(
    const float* __restrict__ Wo, const float* __restrict__ bo,
    const float* __restrict__ mask, float* __restrict__ out)
{
    extern __shared__ uint32_t dsm[];

    const int t    = threadIdx.x;
    const int lane = t & 31;
    const int w    = t >> 5;
    const int wm   = w >> 2;
    const int wn   = w & 3;
    const int g    = lane >> 2;
    const int qd   = lane & 3;
    const int m0   = blockIdx.x * 128;
    const int n0   = blockIdx.y * 128;

    float acc[4][4][4];
#pragma unroll
    for (int mt = 0; mt < 4; mt++)
#pragma unroll
        for (int nt = 0; nt < 4; nt++)
#pragma unroll
            for (int e = 0; e < 4; e++) acc[mt][nt][e] = 0.f;

    dense_gemm_body(g_ln, Wo, dsm, acc, m0, n0);

#pragma unroll
    for (int nt = 0; nt < 4; nt++) {
        int col = n0 + wn * 32 + nt * 8 + qd * 2;
        float bx = bo[col], by = bo[col + 1];
#pragma unroll
        for (int mt = 0; mt < 4; mt++) {
            int row = m0 + wm * 64 + mt * 16 + g;
            float mk0 = mask[row], mk1 = mask[row + 8];
            float v0 = acc[mt][nt][0] + bx;
            float v1 = acc[mt][nt][1] + by;
            float v2 = acc[mt][nt][2] + bx;
            float v3 = acc[mt][nt][3] + by;
            v0 = (v0 >= 0.f ? v0 : 0.01f * v0) * mk0;
            v1 = (v1 >= 0.f ? v1 : 0.01f * v1) * mk0;
            v2 = (v2 >= 0.f ? v2 : 0.01f * v2) * mk1;
            v3 = (v3 >= 0.f ? v3 : 0.01f * v3) * mk1;
            float2 u0 = {v0, v1};
            float2 u1 = {v2, v3};
            *(float2*)&out[(size_t)row * DD + col]       = u0;
            *(float2*)&out[(size_t)(row + 8) * DD + col] = u1;
        }
    }
}

// =========================================================================
// Flash attention: grid=(S/256, B*H), 256 thr (8 warps), 32 q-rows/warp
// (2 m-tiles -> each K/V fragment feeds 2 mma; LDS/mma 2.5 -> 1.5).
// Q/K/V pre-rounded to tf32 by qkv epilogue -> staging is pure uint4 copy.
// K/V double-buffered with register prefetch; 1 syncthreads/iter.
// =========================================================================
#define QST 68
#define VST 72
#define QTILE 256
#define KBUF_W (64*QST)
#define VBUF_W (64*VST)
// Qp | Kp[2] | Vp[2] | Pp | Ms[2]
#define ATT_SMEM_WORDS (QTILE*QST + 2*KBUF_W + 2*VBUF_W + QTILE*QST + 2*64)
#define ATT_SMEM_BYTES (ATT_SMEM_WORDS * 4)   // 211456

__global__ __launch_bounds__(256, 1) void attn_mma(const float* __restrict__ mask)
{
    extern __shared__ uint32_t smw[];
    uint32_t* Qp = smw;                          // QTILE*QST
    uint32_t* Kp = Qp + QTILE*QST;               // 2 * KBUF_W
    uint32_t* Vp = Kp + 2*KBUF_W;                // 2 * VBUF_W
    uint32_t* Pp = Vp + 2*VBUF_W;                // QTILE*QST
    float*    Ms = (float*)(Pp + QTILE*QST);     // 2 * 64

    const int t    = threadIdx.x;
    const int lane = t & 31;
    const int wq   = t >> 5;            // warp -> 32 q-rows
    const int g    = lane >> 2;
    const int qd   = lane & 3;

    const int q0 = blockIdx.x * QTILE;
    const int bh = blockIdx.y;
    const int b  = bh >> 4;
    const int h  = bh & 15;

    const float* Qb = g_Q + ((size_t)bh * SS + q0) * HD;
    const float* Kb = g_K + (size_t)bh * SS * HD;
    const float* Vb = g_V + (size_t)bh * SS * HD;
    const float* mb = mask + (size_t)b * SS;

    const int srow = t >> 4;            // 0..15
    const int skc  = t & 15;

    // ---- stage Q tile (256x64): pure copy (already tf32-rounded) ----
#pragma unroll
    for (int i = 0; i < 16; i++) {
        int idx = t + i * 256;              // 4096 float4
        int row = idx >> 4, kc = idx & 15;
        uint4 u = *(const uint4*)&Qb[(size_t)row * HD + kc * 4];
        *(uint4*)&Qp[row * QST + kc * 4] = u;
    }

    float mi[2][2], li[2][2];
#pragma unroll
    for (int mt = 0; mt < 2; mt++) {
        mi[mt][0] = mi[mt][1] = -1e30f;
        li[mt][0] = li[mt][1] = 0.f;
    }
    float o[2][8][4];
#pragma unroll
    for (int mt = 0; mt < 2; mt++)
#pragma unroll
        for (int nt = 0; nt < 8; nt++)
#pragma unroll
            for (int e = 0; e < 4; e++) o[mt][nt][e] = 0.f;

    const int arow0 = (wq * 32 + g) * QST;        // m-tile 0 frag row base
    const int arow1 = arow0 + 16 * QST;           // m-tile 1

    // ---- prologue: prefetch + stage KV tile 0 into buffer 0 ----
    uint4 rk[4], rv[4]; float rm = 0.f;
#pragma unroll
    for (int i = 0; i < 4; i++) {
        int row = srow + i * 16;
        rk[i] = *(const uint4*)&Kb[(size_t)row * HD + skc * 4];
        rv[i] = *(const uint4*)&Vb[(size_t)row * HD + skc * 4];
    }
    if (t < 64) rm = mb[t];
#pragma unroll
    for (int i = 0; i < 4; i++) {
        int row = srow + i * 16;
        *(uint4*)&Kp[row * QST + skc * 4] = rk[i];
        *(uint4*)&Vp[row * VST + skc * 4] = rv[i];
    }
    if (t < 64) Ms[t] = rm;
    __syncthreads();

    for (int j = 0; j < SS / 64; j++) {
        const int buf = j & 1;
        const uint32_t* Kc = Kp + buf * KBUF_W;
        const uint32_t* Vc = Vp + buf * VBUF_W;
        const float*    Mc = Ms + buf * 64;
        const bool nxt = (j + 1) < (SS / 64);

        // ---- issue next tile's global loads (hidden by the mma below) ----
        if (nxt) {
            const int kv0 = (j + 1) * 64;
#pragma unroll
            for (int i = 0; i < 4; i++) {
                int row = kv0 + srow + i * 16;
                rk[i] = *(const uint4*)&Kb[(size_t)row * HD + skc * 4];
                rv[i] = *(const uint4*)&Vb[(size_t)row * HD + skc * 4];
            }
            if (t < 64) rm = mb[kv0 + t];
        }

        // ---- S = Q K^T  (2 m-tiles share every K fragment) ----
        float s[2][8][4];
#pragma unroll
        for (int mt = 0; mt < 2; mt++)
#pragma unroll
            for (int nt = 0; nt < 8; nt++)
#pragma unroll
                for (int e = 0; e < 4; e++) s[mt][nt][e] = 0.f;

#pragma unroll
        for (int kt = 0; kt < 8; kt++) {
            uint32_t a0[4], a1[4];
            int p0 = arow0 + kt * 8 + qd;
            a0[0] = Qp[p0];
            a0[1] = Qp[p0 + 8 * QST];
            a0[2] = Qp[p0 + 4];
            a0[3] = Qp[p0 + 8 * QST + 4];
            int p1 = arow1 + kt * 8 + qd;
            a1[0] = Qp[p1];
            a1[1] = Qp[p1 + 8 * QST];
            a1[2] = Qp[p1 + 4];
            a1[3] = Qp[p1 + 8 * QST + 4];
            const int bb = g * QST + kt * 8 + qd;
#pragma unroll
            for (int nt = 0; nt < 8; nt++) {
                uint32_t bf[2];
                int q = bb + nt * 8 * QST;
                bf[0] = Kc[q];
                bf[1] = Kc[q + 4];
                mma8(s[0][nt], a0, bf);
                mma8(s[1][nt], a1, bf);
            }
        }

        // ---- scale + mask + online softmax (per m-tile) ----
#pragma unroll
        for (int mt = 0; mt < 2; mt++) {
            float mx0 = -1e30f, mx1 = -1e30f;
#pragma unroll
            for (int nt = 0; nt < 8; nt++) {
#pragma unroll
                for (int e = 0; e < 2; e++) {
                    int col = nt * 8 + qd * 2 + e;
                    float madd = (1.0f - Mc[col]) * -10000.0f;
                    s[mt][nt][e]     = s[mt][nt][e]     * 0.125f + madd;
                    s[mt][nt][2 + e] = s[mt][nt][2 + e] * 0.125f + madd;
                    mx0 = fmaxf(mx0, s[mt][nt][e]);
                    mx1 = fmaxf(mx1, s[mt][nt][2 + e]);
                }
            }
            mx0 = fmaxf(mx0, __shfl_xor_sync(0xffffffffu, mx0, 1));
            mx0 = fmaxf(mx0, __shfl_xor_sync(0xffffffffu, mx0, 2));
            mx1 = fmaxf(mx1, __shfl_xor_sync(0xffffffffu, mx1, 1));
            mx1 = fmaxf(mx1, __shfl_xor_sync(0xffffffffu, mx1, 2));

            float mn0 = fmaxf(mi[mt][0], mx0), mn1 = fmaxf(mi[mt][1], mx1);
            float c0 = __expf(mi[mt][0] - mn0), c1 = __expf(mi[mt][1] - mn1);
            mi[mt][0] = mn0; mi[mt][1] = mn1;

            float rs0 = 0.f, rs1 = 0.f;
#pragma unroll
            for (int nt = 0; nt < 8; nt++) {
#pragma unroll
                for (int e = 0; e < 2; e++) {
                    s[mt][nt][e]     = __expf(s[mt][nt][e]     - mn0);
                    s[mt][nt][2 + e] = __expf(s[mt][nt][2 + e] - mn1);
                    rs0 += s[mt][nt][e];
                    rs1 += s[mt][nt][2 + e];
                }
            }
            rs0 += __shfl_xor_sync(0xffffffffu, rs0, 1);
            rs0 += __shfl_xor_sync(0xffffffffu, rs0, 2);
            rs1 += __shfl_xor_sync(0xffffffffu, rs1, 1);
            rs1 += __shfl_xor_sync(0xffffffffu, rs1, 2);
            li[mt][0] = li[mt][0] * c0 + rs0;
            li[mt][1] = li[mt][1] * c1 + rs1;
#pragma unroll
            for (int nt = 0; nt < 8; nt++) {
                o[mt][nt][0] *= c0; o[mt][nt][1] *= c0;
                o[mt][nt][2] *= c1; o[mt][nt][3] *= c1;
            }
        }

        // ---- stage P (warp-private rows), plain layout ----
#pragma unroll
        for (int mt = 0; mt < 2; mt++) {
            int ar = mt ? arow1 : arow0;
#pragma unroll
            for (int nt = 0; nt < 8; nt++) {
                int pcol = nt * 8 + qd * 2;
                uint2 u0 = {f2tf(s[mt][nt][0]), f2tf(s[mt][nt][1])};
                uint2 u1 = {f2tf(s[mt][nt][2]), f2tf(s[mt][nt][3])};
                *(uint2*)&Pp[ar + pcol]            = u0;
                *(uint2*)&Pp[ar + 8 * QST + pcol]  = u1;
            }
        }
        __syncwarp();

        // ---- O += P @ V  (2 m-tiles share every V fragment) ----
#pragma unroll
        for (int kt = 0; kt < 8; kt++) {
            uint32_t a0[4], a1[4];
            int p0 = arow0 + kt * 8 + qd;
            a0[0] = Pp[p0];
            a0[1] = Pp[p0 + 8 * QST];
            a0[2] = Pp[p0 + 4];
            a0[3] = Pp[p0 + 8 * QST + 4];
            int p1 = arow1 + kt * 8 + qd;
            a1[0] = Pp[p1];
            a1[1] = Pp[p1 + 8 * QST];
            a1[2] = Pp[p1 + 4];
            a1[3] = Pp[p1 + 8 * QST + 4];
            const int vb0 = (kt * 8 + qd) * VST + g;
            const int vb1 = (kt * 8 + qd + 4) * VST + g;
#pragma unroll
            for (int nt = 0; nt < 8; nt++) {
                uint32_t bf[2];
                bf[0] = Vc[vb0 + nt * 8];
                bf[1] = Vc[vb1 + nt * 8];
                mma8(o[0][nt], a0, bf);
                mma8(o[1][nt], a1, bf);
            }
        }
        __syncwarp();

        // ---- stage next tile into the other buffers ----
        if (nxt) {
            uint32_t* Kn = Kp + (buf ^ 1) * KBUF_W;
            uint32_t* Vn = Vp + (buf ^ 1) * VBUF_W;
#pragma unroll
            for (int i = 0; i < 4; i++) {
                int row = srow + i * 16;
                *(uint4*)&Kn[row * QST + skc * 4] = rk[i];
                *(uint4*)&Vn[row * VST + skc * 4] = rv[i];
            }
            if (t < 64) Ms[(buf ^ 1) * 64 + t] = rm;
        }
        __syncthreads();
    }

    // ---- epilogue: normalize, write ctx[b][s][h*64+d] ----
    float* cb = g_ctx + (size_t)(b * SS) * DD + h * HD;
#pragma unroll
    for (int mt = 0; mt < 2; mt++) {
        float inv0 = 1.0f / li[mt][0], inv1 = 1.0f / li[mt][1];
        int row0 = q0 + wq * 32 + mt * 16 + g;
#pragma unroll
        for (int nt = 0; nt < 8; nt++) {
            int d = nt * 8 + qd * 2;
            float2 u0 = {o[mt][nt][0] * inv0, o[mt][nt][1] * inv0};
            float2 u1 = {o[mt][nt][2] * inv1, o[mt][nt][3] * inv1};
            *(float2*)&cb[(size_t)row0 * DD + d]       = u0;
            *(float2*)&cb[(size_t)(row0 + 8) * DD + d] = u1;
        }
    }
}

// =========================================================================
// Kernel 3: residual add + LayerNorm, one block per row
// =========================================================================
__device__ __forceinline__ float block_reduce_sum(float v, float* sred)
{
    int t = threadIdx.x;
#pragma unroll
    for (int o = 16; o > 0; o >>= 1) v += __shfl_xor_sync(0xffffffffu, v, o);
    if ((t & 31) == 0) sred[t >> 5] = v;
    __syncthreads();
    if (t < 32) {
        float x = (t < 8) ? sred[t] : 0.f;
#pragma unroll
        for (int o = 4; o > 0; o >>= 1) x += __shfl_xor_sync(0xffffffffu, x, o);
        if (t == 0) sred[0] = x;
    }
    __syncthreads();
    float r = sred[0];
    __syncthreads();
    return r;
}

__global__ __launch_bounds__(256) void ln_kernel(
    const float* __restrict__ resid,
    const float* __restrict__ gamma, const float* __restrict__ beta)
{
    __shared__ float sred[8];
    const int row = blockIdx.x;
    const int t = threadIdx.x;

    float4 c4 = *(const float4*)&g_ctx[(size_t)row * DD + t * 4];
    float4 r4 = *(const float4*)&resid[(size_t)row * DD + t * 4];
    float x0 = c4.x + r4.x, x1 = c4.y + r4.y, x2 = c4.z + r4.z, x3 = c4.w + r4.w;

    float mu = block_reduce_sum(x0 + x1 + x2 + x3, sred) * (1.0f / DD);
    float d0 = x0 - mu, d1 = x1 - mu, d2 = x2 - mu, d3 = x3 - mu;
    float var = block_reduce_sum(d0 * d0 + d1 * d1 + d2 * d2 + d3 * d3, sred) * (1.0f / DD);
    float rstd = rsqrtf(var + 1e-5f);

    float4 g4 = *(const float4*)&gamma[t * 4];
    float4 b4 = *(const float4*)&beta[t * 4];
    float4 res;
    res.x = d0 * rstd * g4.x + b4.x;
    res.y = d1 * rstd * g4.y + b4.y;
    res.z = d2 * rstd * g4.z + b4.z;
    res.w = d3 * rstd * g4.w + b4.w;
    *(float4*)&g_ln[(size_t)row * DD + t * 4] = res;
}

// =========================================================================
// launch
// =========================================================================
extern "C" void kernel_launch(void* const* d_in, const int* in_sizes, int n_in,
                              void* d_out, int out_size)
{
    const float* inputs = (const float*)d_in[0];
    const float* mask   = (const float*)d_in[1];
    const float* Wq = (const float*)d_in[2];
    const float* bq = (const float*)d_in[3];
    const float* Wk = (const float*)d_in[4];
    const float* bk = (const float*)d_in[5];
    const float* Wv = (const float*)d_in[6];
    const float* bv = (const float*)d_in[7];
    const float* Wo = (const float*)d_in[8];
    const float* bo = (const float*)d_in[9];
    const float* ln_g = (const float*)d_in[10];
    const float* ln_b = (const float*)d_in[11];
    float* out = (float*)d_out;

    cudaFuncSetAttribute(qkv_mma, cudaFuncAttributeMaxDynamicSharedMemorySize, DSM_BYTES);
    cudaFuncSetAttribute(out_mma, cudaFuncAttributeMaxDynamicSharedMemorySize, DSM_BYTES);
    cudaFuncSetAttribute(attn_mma, cudaFuncAttributeMaxDynamicSharedMemorySize, ATT_SMEM_BYTES);

    qkv_mma<<<dim3(NTOK / 128, DD / 128, 3), 256, DSM_BYTES>>>(inputs, Wq, bq, Wk, bk, Wv, bv);
    attn_mma<<<dim3(SS / QTILE, BB * HH), 256, ATT_SMEM_BYTES>>>(mask);
    ln_kernel<<<NTOK, 256>>>(inputs, ln_g, ln_b);
    out_mma<<<dim3(NTOK / 128, DD / 128), 256, DSM_BYTES>>>(Wo, bo, mask, out);
}

// round 12
// speedup vs baseline: 1.8722x; 1.4569x over previous
#include <cuda_runtime.h>
#include <cuda_fp16.h>
#include <cstdint>

#define BB 4
#define SS 2048
#define DD 1024
#define HH 16
#define HD 64
#define NTOK (BB*SS)          // 8192

// ---------------- scratch (device globals; no allocation) ----------------
__device__ __half g_Q[(size_t)BB*HH*SS*HD];    // [B,H,S,HD] fp16
__device__ __half g_K[(size_t)BB*HH*SS*HD];
__device__ __half g_V[(size_t)BB*HH*SS*HD];
__device__ __half g_VT[(size_t)BB*HH*SS*HD];   // [B,H,HD,S] fp16 (V transposed)
__device__ float  g_ctx[(size_t)NTOK*DD];      // [B,S,D]
__device__ float  g_ln[(size_t)NTOK*DD];       // [B,S,D]

// ---------------- fp16 helpers ----------------
__device__ __forceinline__ uint32_t f2h2(float lo, float hi) {
    __half2 h = __floats2half2_rn(lo, hi);
    return *(uint32_t*)&h;
}
__device__ __forceinline__ void mma16(float d[4], const uint32_t a[4], const uint32_t b[2]) {
    asm("mma.sync.aligned.m16n8k16.row.col.f32.f16.f16.f32 "
        "{%0,%1,%2,%3}, {%4,%5,%6,%7}, {%8,%9}, {%0,%1,%2,%3};"
        : "+f"(d[0]), "+f"(d[1]), "+f"(d[2]), "+f"(d[3])
        : "r"(a[0]), "r"(a[1]), "r"(a[2]), "r"(a[3]), "r"(b[0]), "r"(b[1]));
}

// =========================================================================
// Dense GEMM (fp16 mma): CTA 128x128, 256 thr (8 warps = 2m x 4n),
// warp 64x32.  k-chunks of 32 halves (16 words/row, stride 20 -> frag LDS
// banks g*20+qd all distinct).  Double-buffer + register prefetch.
// =========================================================================
#define DSTW 20
#define DBUF_W (128*DSTW)                 // 2560 words per tensor per stage
#define DSM_BYTES (4*DBUF_W*4)            // 40960 B
#define NCHUNK (DD/32)                    // 32

__device__ __forceinline__ void dense_body(
    const float* __restrict__ Asrc, const float* __restrict__ W,
    uint32_t* dsm, float acc[4][4][4], int m0, int n0)
{
    const int t    = threadIdx.x;
    const int lane = t & 31;
    const int w    = t >> 5;
    const int wm   = w >> 2;
    const int wn   = w & 3;
    const int g    = lane >> 2;
    const int qd   = lane & 3;

    const int srow = t >> 2;        // 0..63 (+64 for i=1)
    const int skc  = t & 3;         // uint4 (8 halves) chunk in row
    const float* aptr = Asrc + (size_t)(m0 + srow) * DD + skc * 8;
    const float* bptr = W    + (size_t)(n0 + srow) * DD + skc * 8;

    float4 ra[2][2], rb[2][2];
#pragma unroll
    for (int i = 0; i < 2; i++) {
        ra[i][0] = *(const float4*)(aptr + (size_t)i * 64 * DD);
        ra[i][1] = *(const float4*)(aptr + (size_t)i * 64 * DD + 4);
        rb[i][0] = *(const float4*)(bptr + (size_t)i * 64 * DD);
        rb[i][1] = *(const float4*)(bptr + (size_t)i * 64 * DD + 4);
    }
    {
        uint32_t* Ap = dsm;
        uint32_t* Bp = dsm + DBUF_W;
#pragma unroll
        for (int i = 0; i < 2; i++) {
            uint4 ua = {f2h2(ra[i][0].x, ra[i][0].y), f2h2(ra[i][0].z, ra[i][0].w),
                        f2h2(ra[i][1].x, ra[i][1].y), f2h2(ra[i][1].z, ra[i][1].w)};
            *(uint4*)&Ap[(srow + i * 64) * DSTW + skc * 4] = ua;
            uint4 ub = {f2h2(rb[i][0].x, rb[i][0].y), f2h2(rb[i][0].z, rb[i][0].w),
                        f2h2(rb[i][1].x, rb[i][1].y), f2h2(rb[i][1].z, rb[i][1].w)};
            *(uint4*)&Bp[(srow + i * 64) * DSTW + skc * 4] = ub;
        }
    }
    __syncthreads();

    for (int j = 0; j < NCHUNK; j++) {
        const int st = j & 1;
        uint32_t* Ac = dsm + (st ? 2 * DBUF_W : 0);
        uint32_t* Bc = Ac + DBUF_W;
        const bool nxt = (j + 1) < NCHUNK;

        if (nxt) {
            const int k0 = (j + 1) * 32;
#pragma unroll
            for (int i = 0; i < 2; i++) {
                ra[i][0] = *(const float4*)(aptr + k0 + (size_t)i * 64 * DD);
                ra[i][1] = *(const float4*)(aptr + k0 + (size_t)i * 64 * DD + 4);
                rb[i][0] = *(const float4*)(bptr + k0 + (size_t)i * 64 * DD);
                rb[i][1] = *(const float4*)(bptr + k0 + (size_t)i * 64 * DD + 4);
            }
        }

#pragma unroll
        for (int kt = 0; kt < 2; kt++) {
            uint32_t a[4][4];
            const int ab = (wm * 64 + g) * DSTW + kt * 8 + qd;
#pragma unroll
            for (int mt = 0; mt < 4; mt++) {
                int p = ab + mt * 16 * DSTW;
                a[mt][0] = Ac[p];
                a[mt][1] = Ac[p + 8 * DSTW];
                a[mt][2] = Ac[p + 4];
                a[mt][3] = Ac[p + 8 * DSTW + 4];
            }
            const int bb = (wn * 32 + g) * DSTW + kt * 8 + qd;
#pragma unroll
            for (int nt = 0; nt < 4; nt++) {
                uint32_t b2[2];
                int p = bb + nt * 8 * DSTW;
                b2[0] = Bc[p];
                b2[1] = Bc[p + 4];
#pragma unroll
                for (int mt = 0; mt < 4; mt++)
                    mma16(acc[mt][nt], a[mt], b2);
            }
        }

        if (nxt) {
            uint32_t* An = dsm + (st ? 0 : 2 * DBUF_W);
            uint32_t* Bn = An + DBUF_W;
#pragma unroll
            for (int i = 0; i < 2; i++) {
                uint4 ua = {f2h2(ra[i][0].x, ra[i][0].y), f2h2(ra[i][0].z, ra[i][0].w),
                            f2h2(ra[i][1].x, ra[i][1].y), f2h2(ra[i][1].z, ra[i][1].w)};
                *(uint4*)&An[(srow + i * 64) * DSTW + skc * 4] = ua;
                uint4 ub = {f2h2(rb[i][0].x, rb[i][0].y), f2h2(rb[i][0].z, rb[i][0].w),
                            f2h2(rb[i][1].x, rb[i][1].y), f2h2(rb[i][1].z, rb[i][1].w)};
                *(uint4*)&Bn[(srow + i * 64) * DSTW + skc * 4] = ub;
            }
        }
        __syncthreads();
    }
}

__global__ __launch_bounds__(256, 2) void qkv_mma(
    const float* __restrict__ X,
    const float* __restrict__ Wq, const float* __restrict__ bq,
    const float* __restrict__ Wk, const float* __restrict__ bk,
    const float* __restrict__ Wv, const float* __restrict__ bv)
{
    const float* W; const float* bias; __half* outp;
    if (blockIdx.z == 0)      { W = Wq; bias = bq; outp = g_Q; }
    else if (blockIdx.z == 1) { W = Wk; bias = bk; outp = g_K; }
    else                      { W = Wv; bias = bv; outp = g_V; }

    extern __shared__ uint32_t dsm[];

    const int t    = threadIdx.x;
    const int lane = t & 31;
    const int w    = t >> 5;
    const int wm   = w >> 2;
    const int wn   = w & 3;
    const int g    = lane >> 2;
    const int qd   = lane & 3;
    const int m0   = blockIdx.x * 128;
    const int n0   = blockIdx.y * 128;

    float acc[4][4][4];
#pragma unroll
    for (int mt = 0; mt < 4; mt++)
#pragma unroll
        for (int nt = 0; nt < 4; nt++)
#pragma unroll
            for (int e = 0; e < 4; e++) acc[mt][nt][e] = 0.f;

    dense_body(X, W, dsm, acc, m0, n0);

    // epilogue: bias add, fp16 convert, scatter to [B,H,S,HD]
    const int bidx  = m0 >> 11;
    const int sbase = m0 & (SS - 1);
#pragma unroll
    for (int nt = 0; nt < 4; nt++) {
        int col = n0 + wn * 32 + nt * 8 + qd * 2;
        int h = col >> 6, d = col & 63;
        float bx = bias[col], by = bias[col + 1];
        __half* obase = outp + ((size_t)(bidx * HH + h) * SS) * HD + d;
#pragma unroll
        for (int mt = 0; mt < 4; mt++) {
            int s = sbase + wm * 64 + mt * 16 + g;
            __half2 v0 = __floats2half2_rn(acc[mt][nt][0] + bx, acc[mt][nt][1] + by);
            __half2 v1 = __floats2half2_rn(acc[mt][nt][2] + bx, acc[mt][nt][3] + by);
            *(__half2*)&obase[(size_t)s * HD]       = v0;
            *(__half2*)&obase[(size_t)(s + 8) * HD] = v1;
        }
    }
}

__global__ __launch_bounds__(256, 2) void out_mma(
    const float* __restrict__ Wo, const float* __restrict__ bo,
    const float* __restrict__ mask, float* __restrict__ out)
{
    extern __shared__ uint32_t dsm[];

    const int t    = threadIdx.x;
    const int lane = t & 31;
    const int w    = t >> 5;
    const int wm   = w >> 2;
    const int wn   = w & 3;
    const int g    = lane >> 2;
    const int qd   = lane & 3;
    const int m0   = blockIdx.x * 128;
    const int n0   = blockIdx.y * 128;

    float acc[4][4][4];
#pragma unroll
    for (int mt = 0; mt < 4; mt++)
#pragma unroll
        for (int nt = 0; nt < 4; nt++)
#pragma unroll
            for (int e = 0; e < 4; e++) acc[mt][nt][e] = 0.f;

    dense_body(g_ln, Wo, dsm, acc, m0, n0);

#pragma unroll
    for (int nt = 0; nt < 4; nt++) {
        int col = n0 + wn * 32 + nt * 8 + qd * 2;
        float bx = bo[col], by = bo[col + 1];
#pragma unroll
        for (int mt = 0; mt < 4; mt++) {
            int row = m0 + wm * 64 + mt * 16 + g;
            float mk0 = mask[row], mk1 = mask[row + 8];
            float v0 = acc[mt][nt][0] + bx;
            float v1 = acc[mt][nt][1] + by;
            float v2 = acc[mt][nt][2] + bx;
            float v3 = acc[mt][nt][3] + by;
            v0 = (v0 >= 0.f ? v0 : 0.01f * v0) * mk0;
            v1 = (v1 >= 0.f ? v1 : 0.01f * v1) * mk0;
            v2 = (v2 >= 0.f ? v2 : 0.01f * v2) * mk1;
            v3 = (v3 >= 0.f ? v3 : 0.01f * v3) * mk1;
            float2 u0 = {v0, v1};
            float2 u1 = {v2, v3};
            *(float2*)&out[(size_t)row * DD + col]       = u0;
            *(float2*)&out[(size_t)(row + 8) * DD + col] = u1;
        }
    }
}

// =========================================================================
// V transpose: g_V [bh][s][d] -> g_VT [bh][d][s], 64x64 half tiles.
// Tile row stride 72 halves (144 B, 16B-aligned for every row); 16-byte
// chunks XOR-swizzled by (row>>3) so transposed reads are conflict-free.
// =========================================================================
__global__ __launch_bounds__(256) void v_transpose()
{
    __shared__ __half tile[64 * 72];
    const int t  = threadIdx.x;
    const int s0 = blockIdx.x * 64;
    const int bh = blockIdx.y;

    const __half* src = g_V + ((size_t)bh * SS + s0) * HD;
#pragma unroll
    for (int i = 0; i < 2; i++) {
        int idx = t + i * 256;
        int row = idx >> 3, kc = idx & 7;
        uint4 v = *(const uint4*)&src[(size_t)row * HD + kc * 8];
        *(uint4*)&tile[row * 72 + ((kc ^ (row >> 3)) * 8)] = v;
    }
    __syncthreads();

    __half* dst = g_VT + (size_t)bh * HD * SS + s0;
#pragma unroll
    for (int i = 0; i < 2; i++) {
        int idx = t + i * 256;
        int d = idx >> 3, sc = idx & 7;     // d: head dim, sc: 8-row group
        __align__(16) __half h[8];
#pragma unroll
        for (int k = 0; k < 8; k++)
            h[k] = tile[(sc * 8 + k) * 72 + (((d >> 3) ^ sc) * 8) + (d & 7)];
        *(uint4*)&dst[(size_t)d * SS + sc * 8] = *(uint4*)h;
    }
}

// =========================================================================
// Flash attention (fp16 mma): grid=(S/256, B*H), 256 thr, 32 q-rows/warp.
// Tiles: rows of 64 halves = 32 words, stride 36 (banks 4g+qd distinct).
// K [kv][d]; VT [d][kv] (pre-transposed) -> PV B-frags contiguous half2.
// Double-buffered K/VT with register prefetch.
// =========================================================================
#define ASTW 36
#define QTILE 256
#define KBUF_W (64*ASTW)
#define ATT_SMEM_WORDS (QTILE*ASTW + 2*KBUF_W + 2*KBUF_W + QTILE*ASTW + 2*64)
#define ATT_SMEM_BYTES (ATT_SMEM_WORDS * 4)   // 111104

__global__ __launch_bounds__(256, 1) void attn_mma(const float* __restrict__ mask)
{
    extern __shared__ uint32_t smw[];
    uint32_t* Qp  = smw;                         // QTILE*ASTW
    uint32_t* Kp  = Qp + QTILE*ASTW;             // 2 * KBUF_W
    uint32_t* Vtp = Kp + 2*KBUF_W;               // 2 * KBUF_W
    uint32_t* Pp  = Vtp + 2*KBUF_W;              // QTILE*ASTW
    float*    Ms  = (float*)(Pp + QTILE*ASTW);   // 2 * 64

    const int t    = threadIdx.x;
    const int lane = t & 31;
    const int wq   = t >> 5;
    const int g    = lane >> 2;
    const int qd   = lane & 3;

    const int q0 = blockIdx.x * QTILE;
    const int bh = blockIdx.y;
    const int b  = bh >> 4;
    const int h  = bh & 15;

    const __half* Qb  = g_Q  + ((size_t)bh * SS + q0) * HD;
    const __half* Kb  = g_K  + (size_t)bh * SS * HD;
    const __half* VTb = g_VT + (size_t)bh * HD * SS;
    const float*  mb  = mask + (size_t)b * SS;

    // ---- stage Q (256 x 64 halves): pure copy ----
#pragma unroll
    for (int i = 0; i < 8; i++) {
        int idx = t + i * 256;                    // 2048 uint4
        int row = idx >> 3, kc = idx & 7;
        uint4 u = *(const uint4*)&Qb[(size_t)row * HD + kc * 8];
        *(uint4*)&Qp[row * ASTW + kc * 4] = u;
    }

    float mi[2][2], li[2][2];
#pragma unroll
    for (int mt = 0; mt < 2; mt++) {
        mi[mt][0] = mi[mt][1] = -1e30f;
        li[mt][0] = li[mt][1] = 0.f;
    }
    float o[2][8][4];
#pragma unroll
    for (int mt = 0; mt < 2; mt++)
#pragma unroll
        for (int nt = 0; nt < 8; nt++)
#pragma unroll
            for (int e = 0; e < 4; e++) o[mt][nt][e] = 0.f;

    const int arow0 = (wq * 32 + g) * ASTW;
    const int arow1 = arow0 + 16 * ASTW;

    // ---- prologue: prefetch + stage KV tile 0 ----
    uint4 rk[2], rv[2]; float rm = 0.f;
#pragma unroll
    for (int i = 0; i < 2; i++) {
        int idx = t + i * 256;
        int row = idx >> 3, kc = idx & 7;
        rk[i] = *(const uint4*)&Kb[(size_t)row * HD + kc * 8];
        rv[i] = *(const uint4*)&VTb[(size_t)row * SS + kc * 8];
    }
    if (t < 64) rm = mb[t];
#pragma unroll
    for (int i = 0; i < 2; i++) {
        int idx = t + i * 256;
        int row = idx >> 3, kc = idx & 7;
        *(uint4*)&Kp[row * ASTW + kc * 4]  = rk[i];
        *(uint4*)&Vtp[row * ASTW + kc * 4] = rv[i];
    }
    if (t < 64) Ms[t] = rm;
    __syncthreads();

    for (int j = 0; j < SS / 64; j++) {
        const int buf = j & 1;
        const uint32_t* Kc  = Kp  + buf * KBUF_W;
        const uint32_t* Vtc = Vtp + buf * KBUF_W;
        const float*    Mc  = Ms  + buf * 64;
        const bool nxt = (j + 1) < (SS / 64);

        if (nxt) {
            const int kv0 = (j + 1) * 64;
#pragma unroll
            for (int i = 0; i < 2; i++) {
                int idx = t + i * 256;
                int row = idx >> 3, kc = idx & 7;
                rk[i] = *(const uint4*)&Kb[(size_t)(kv0 + row) * HD + kc * 8];
                rv[i] = *(const uint4*)&VTb[(size_t)row * SS + kv0 + kc * 8];
            }
            if (t < 64) rm = mb[kv0 + t];
        }

        // ---- S = Q K^T (fp16 k16, 4 k-tiles over d=64) ----
        float s[2][8][4];
#pragma unroll
        for (int mt = 0; mt < 2; mt++)
#pragma unroll
            for (int nt = 0; nt < 8; nt++)
#pragma unroll
                for (int e = 0; e < 4; e++) s[mt][nt][e] = 0.f;

#pragma unroll
        for (int kt = 0; kt < 4; kt++) {
            uint32_t a0[4], a1[4];
            int p0 = arow0 + kt * 8 + qd;
            a0[0] = Qp[p0];
            a0[1] = Qp[p0 + 8 * ASTW];
            a0[2] = Qp[p0 + 4];
            a0[3] = Qp[p0 + 8 * ASTW + 4];
            int p1 = arow1 + kt * 8 + qd;
            a1[0] = Qp[p1];
            a1[1] = Qp[p1 + 8 * ASTW];
            a1[2] = Qp[p1 + 4];
            a1[3] = Qp[p1 + 8 * ASTW + 4];
            const int bb = g * ASTW + kt * 8 + qd;
#pragma unroll
            for (int nt = 0; nt < 8; nt++) {
                uint32_t bf[2];
                int q = bb + nt * 8 * ASTW;
                bf[0] = Kc[q];
                bf[1] = Kc[q + 4];
                mma16(s[0][nt], a0, bf);
                mma16(s[1][nt], a1, bf);
            }
        }

        // ---- scale + mask + online softmax ----
#pragma unroll
        for (int mt = 0; mt < 2; mt++) {
            float mx0 = -1e30f, mx1 = -1e30f;
#pragma unroll
            for (int nt = 0; nt < 8; nt++) {
#pragma unroll
                for (int e = 0; e < 2; e++) {
                    int col = nt * 8 + qd * 2 + e;
                    float madd = (1.0f - Mc[col]) * -10000.0f;
                    s[mt][nt][e]     = s[mt][nt][e]     * 0.125f + madd;
                    s[mt][nt][2 + e] = s[mt][nt][2 + e] * 0.125f + madd;
                    mx0 = fmaxf(mx0, s[mt][nt][e]);
                    mx1 = fmaxf(mx1, s[mt][nt][2 + e]);
                }
            }
            mx0 = fmaxf(mx0, __shfl_xor_sync(0xffffffffu, mx0, 1));
            mx0 = fmaxf(mx0, __shfl_xor_sync(0xffffffffu, mx0, 2));
            mx1 = fmaxf(mx1, __shfl_xor_sync(0xffffffffu, mx1, 1));
            mx1 = fmaxf(mx1, __shfl_xor_sync(0xffffffffu, mx1, 2));

            float mn0 = fmaxf(mi[mt][0], mx0), mn1 = fmaxf(mi[mt][1], mx1);
            float c0 = __expf(mi[mt][0] - mn0), c1 = __expf(mi[mt][1] - mn1);
            mi[mt][0] = mn0; mi[mt][1] = mn1;

            float rs0 = 0.f, rs1 = 0.f;
#pragma unroll
            for (int nt = 0; nt < 8; nt++) {
#pragma unroll
                for (int e = 0; e < 2; e++) {
                    s[mt][nt][e]     = __expf(s[mt][nt][e]     - mn0);
                    s[mt][nt][2 + e] = __expf(s[mt][nt][2 + e] - mn1);
                    rs0 += s[mt][nt][e];
                    rs1 += s[mt][nt][2 + e];
                }
            }
            rs0 += __shfl_xor_sync(0xffffffffu, rs0, 1);
            rs0 += __shfl_xor_sync(0xffffffffu, rs0, 2);
            rs1 += __shfl_xor_sync(0xffffffffu, rs1, 1);
            rs1 += __shfl_xor_sync(0xffffffffu, rs1, 2);
            li[mt][0] = li[mt][0] * c0 + rs0;
            li[mt][1] = li[mt][1] * c1 + rs1;
#pragma unroll
            for (int nt = 0; nt < 8; nt++) {
                o[mt][nt][0] *= c0; o[mt][nt][1] *= c0;
                o[mt][nt][2] *= c1; o[mt][nt][3] *= c1;
            }
        }

        // ---- stage P as fp16 (warp-private rows) ----
#pragma unroll
        for (int mt = 0; mt < 2; mt++) {
            int ar = mt ? arow1 : arow0;
#pragma unroll
            for (int nt = 0; nt < 8; nt++) {
                int wrd = ar + nt * 4 + qd;
                Pp[wrd]            = f2h2(s[mt][nt][0], s[mt][nt][1]);
                Pp[wrd + 8 * ASTW] = f2h2(s[mt][nt][2], s[mt][nt][3]);
            }
        }
        __syncwarp();

        // ---- O += P @ V (B-frags from VT [d][kv], contiguous kv pairs) ----
#pragma unroll
        for (int kt = 0; kt < 4; kt++) {
            uint32_t a0[4], a1[4];
            int p0 = arow0 + kt * 8 + qd;
            a0[0] = Pp[p0];
            a0[1] = Pp[p0 + 8 * ASTW];
            a0[2] = Pp[p0 + 4];
            a0[3] = Pp[p0 + 8 * ASTW + 4];
            int p1 = arow1 + kt * 8 + qd;
            a1[0] = Pp[p1];
            a1[1] = Pp[p1 + 8 * ASTW];
            a1[2] = Pp[p1 + 4];
            a1[3] = Pp[p1 + 8 * ASTW + 4];
            const int bb = g * ASTW + kt * 8 + qd;
#pragma unroll
            for (int nt = 0; nt < 8; nt++) {
                uint32_t bf[2];
                int q = bb + nt * 8 * ASTW;
                bf[0] = Vtc[q];
                bf[1] = Vtc[q + 4];
                mma16(o[0][nt], a0, bf);
                mma16(o[1][nt], a1, bf);
            }
        }
        __syncwarp();

        // ---- stage next tile into the other buffers ----
        if (nxt) {
            uint32_t* Kn  = Kp  + (buf ^ 1) * KBUF_W;
            uint32_t* Vtn = Vtp + (buf ^ 1) * KBUF_W;
#pragma unroll
            for (int i = 0; i < 2; i++) {
                int idx = t + i * 256;
                int row = idx >> 3, kc = idx & 7;
                *(uint4*)&Kn[row * ASTW + kc * 4]  = rk[i];
                *(uint4*)&Vtn[row * ASTW + kc * 4] = rv[i];
            }
            if (t < 64) Ms[(buf ^ 1) * 64 + t] = rm;
        }
        __syncthreads();
    }

    // ---- epilogue: normalize, write ctx[b][s][h*64+d] ----
    float* cb = g_ctx + (size_t)(b * SS) * DD + h * HD;
#pragma unroll
    for (int mt = 0; mt < 2; mt++) {
        float inv0 = 1.0f / li[mt][0], inv1 = 1.0f / li[mt][1];
        int row0 = q0 + wq * 32 + mt * 16 + g;
#pragma unroll
        for (int nt = 0; nt < 8; nt++) {
            int d = nt * 8 + qd * 2;
            float2 u0 = {o[mt][nt][0] * inv0, o[mt][nt][1] * inv0};
            float2 u1 = {o[mt][nt][2] * inv1, o[mt][nt][3] * inv1};
            *(float2*)&cb[(size_t)row0 * DD + d]       = u0;
            *(float2*)&cb[(size_t)(row0 + 8) * DD + d] = u1;
        }
    }
}

// =========================================================================
// Kernel: residual add + LayerNorm, one block per row (unchanged)
// =========================================================================
__device__ __forceinline__ float block_reduce_sum(float v, float* sred)
{
    int t = threadIdx.x;
#pragma unroll
    for (int o = 16; o > 0; o >>= 1) v += __shfl_xor_sync(0xffffffffu, v, o);
    if ((t & 31) == 0) sred[t >> 5] = v;
    __syncthreads();
    if (t < 32) {
        float x = (t < 8) ? sred[t] : 0.f;
#pragma unroll
        for (int o = 4; o > 0; o >>= 1) x += __shfl_xor_sync(0xffffffffu, x, o);
        if (t == 0) sred[0] = x;
    }
    __syncthreads();
    float r = sred[0];
    __syncthreads();
    return r;
}

__global__ __launch_bounds__(256) void ln_kernel(
    const float* __restrict__ resid,
    const float* __restrict__ gamma, const float* __restrict__ beta)
{
    __shared__ float sred[8];
    const int row = blockIdx.x;
    const int t = threadIdx.x;

    float4 c4 = *(const float4*)&g_ctx[(size_t)row * DD + t * 4];
    float4 r4 = *(const float4*)&resid[(size_t)row * DD + t * 4];
    float x0 = c4.x + r4.x, x1 = c4.y + r4.y, x2 = c4.z + r4.z, x3 = c4.w + r4.w;

    float mu = block_reduce_sum(x0 + x1 + x2 + x3, sred) * (1.0f / DD);
    float d0 = x0 - mu, d1 = x1 - mu, d2 = x2 - mu, d3 = x3 - mu;
    float var = block_reduce_sum(d0 * d0 + d1 * d1 + d2 * d2 + d3 * d3, sred) * (1.0f / DD);
    float rstd = rsqrtf(var + 1e-5f);

    float4 g4 = *(const float4*)&gamma[t * 4];
    float4 b4 = *(const float4*)&beta[t * 4];
    float4 res;
    res.x = d0 * rstd * g4.x + b4.x;
    res.y = d1 * rstd * g4.y + b4.y;
    res.z = d2 * rstd * g4.z + b4.z;
    res.w = d3 * rstd * g4.w + b4.w;
    *(float4*)&g_ln[(size_t)row * DD + t * 4] = res;
}

// =========================================================================
// launch
// =========================================================================
extern "C" void kernel_launch(void* const* d_in, const int* in_sizes, int n_in,
                              void* d_out, int out_size)
{
    const float* inputs = (const float*)d_in[0];
    const float* mask   = (const float*)d_in[1];
    const float* Wq = (const float*)d_in[2];
    const float* bq = (const float*)d_in[3];
    const float* Wk = (const float*)d_in[4];
    const float* bk = (const float*)d_in[5];
    const float* Wv = (const float*)d_in[6];
    const float* bv = (const float*)d_in[7];
    const float* Wo = (const float*)d_in[8];
    const float* bo = (const float*)d_in[9];
    const float* ln_g = (const float*)d_in[10];
    const float* ln_b = (const float*)d_in[11];
    float* out = (float*)d_out;

    cudaFuncSetAttribute(qkv_mma, cudaFuncAttributeMaxDynamicSharedMemorySize, DSM_BYTES);
    cudaFuncSetAttribute(out_mma, cudaFuncAttributeMaxDynamicSharedMemorySize, DSM_BYTES);
    cudaFuncSetAttribute(attn_mma, cudaFuncAttributeMaxDynamicSharedMemorySize, ATT_SMEM_BYTES);

    qkv_mma<<<dim3(NTOK / 128, DD / 128, 3), 256, DSM_BYTES>>>(inputs, Wq, bq, Wk, bk, Wv, bv);
    v_transpose<<<dim3(SS / 64, BB * HH), 256>>>();
    attn_mma<<<dim3(SS / QTILE, BB * HH), 256, ATT_SMEM_BYTES>>>(mask);
    ln_kernel<<<NTOK, 256>>>(inputs, ln_g, ln_b);
    out_mma<<<dim3(NTOK / 128, DD / 128), 256, DSM_BYTES>>>(Wo, bo, mask, out);
}